// round 3
// baseline (speedup 1.0000x reference)
#include <cuda_runtime.h>
#include <cstdint>

#define NB 128      // CTAs (one per SM, <= 152 on GB300: co-residency guaranteed)
#define NT 256      // threads per CTA
#define BB 128      // batch
#define TT 1024     // seq len
#define FF 64       // features
#define HH 512      // hidden
#define CHUNK 64    // k-chunk staged in smem per pipeline stage
#define KENC (HH + FF)   // 576: h (512) + x (64) concatenated reduction dim

// ---------------- device scratch (no allocations allowed) ----------------
__device__ float g_h[2][HH * BB];          // h state double buffer, layout [j][b]
__device__ float g_xT[TT * FF * BB];       // transposed input [t][f][b]
__device__ unsigned int g_count = 0;       // grid barrier arrive counter
__device__ unsigned int g_gen = 0;         // grid barrier generation

// ---------------- packed f32x2 helpers ----------------
__device__ __forceinline__ unsigned long long pack2(float x, float y) {
    unsigned long long r;
    asm("mov.b64 %0, {%1, %2};" : "=l"(r) : "f"(x), "f"(y));
    return r;
}
__device__ __forceinline__ float2 unpack2(unsigned long long v) {
    float2 r;
    asm("mov.b64 {%0, %1}, %2;" : "=f"(r.x), "=f"(r.y) : "l"(v));
    return r;
}
__device__ __forceinline__ void fma2(unsigned long long& d, unsigned long long a,
                                     unsigned long long b) {
    asm("fma.rn.f32x2 %0, %1, %2, %0;" : "+l"(d) : "l"(a), "l"(b));
}
__device__ __forceinline__ float sigmoidf(float x) {
    return 1.0f / (1.0f + __expf(-x));
}

// ---------------- software grid barrier (persistent kernel) ----------------
__device__ __forceinline__ void grid_barrier(unsigned int* s_gen) {
    __syncthreads();
    if (threadIdx.x == 0) {
        unsigned int target = *s_gen + 1u;
        __threadfence();
        unsigned int t = atomicAdd(&g_count, 1u);
        if (t == NB - 1u) {
            g_count = 0u;
            asm volatile("st.release.gpu.b32 [%0], %1;" :: "l"(&g_gen), "r"(target) : "memory");
        } else {
            unsigned int cur;
            do {
                __nanosleep(20);
                asm volatile("ld.acquire.gpu.b32 %0, [%1];" : "=r"(cur) : "l"(&g_gen) : "memory");
            } while ((int)(cur - target) < 0);
        }
        *s_gen = target;
    }
    __syncthreads();
}

// ---------------- cp.async chunk prefetch: CHUNK*BB floats = 32KB ----------------
__device__ __forceinline__ void prefetch_chunk(unsigned int smem_dst, const float* src, int tid) {
#pragma unroll
    for (int i = 0; i < 8; i++) {
        int off = tid + NT * i;   // 2048 float4 total
        asm volatile("cp.async.cg.shared.global [%0], [%1], 16;"
                     :: "r"(smem_dst + off * 16), "l"(src + off * 4) : "memory");
    }
    asm volatile("cp.async.commit_group;" ::: "memory");
}

struct Acc {
    unsigned long long if0, go0, if1, go1;
};

// gate GEMM over one staged chunk; weights in smem layout [k][col][gate] (16 floats/k)
__device__ __forceinline__ void gate_chunk(const float* hbuf_c, const float* W, int kbase,
                                           int col, int bpair, Acc& a) {
    const float2* hp = (const float2*)hbuf_c + bpair;
    const ulonglong2* wp = (const ulonglong2*)(W + (size_t)kbase * 16 + col * 4);
#pragma unroll 16
    for (int kk = 0; kk < CHUNK; ++kk) {
        float2 h2 = hp[kk * (BB / 2)];
        // per-k stride = 16 floats = 4 ulonglong2 (FIXED: was kk*2, reading wrong weights)
        ulonglong2 w2 = wp[kk * 4];             // {w_i,w_f},{w_g,w_o} at this k
        unsigned long long hb0 = pack2(h2.x, h2.x);
        unsigned long long hb1 = pack2(h2.y, h2.y);
        fma2(a.if0, w2.x, hb0);
        fma2(a.go0, w2.y, hb0);
        fma2(a.if1, w2.x, hb1);
        fma2(a.go1, w2.y, hb1);
    }
}

// one LSTM step (encoder: K=576 incl. x chunk; decoder: K=512 with fused W_eff)
template <bool IS_DEC>
__device__ __forceinline__ void lstm_step(
    const float* hsrc, float* hdst, const float* xsrc,
    const float* W, const float* bias_s,
    float* hbuf, unsigned int hbuf_saddr,
    const float* wout_s, float* yout, float bout_f, bool do_y,
    int tid, int col, int bpair, int j, float& c0, float& c1,
    unsigned int* s_gen)
{
    const int NCH = IS_DEC ? 8 : 9;
    float4 bb = *(const float4*)(bias_s + col * 4);
    Acc a;
    a.if0 = pack2(bb.x, bb.y);
    a.go0 = pack2(bb.z, bb.w);
    a.if1 = a.if0;
    a.go1 = a.go0;
    float yacc = 0.0f;

    prefetch_chunk(hbuf_saddr, hsrc, tid);
    for (int c = 0; c < NCH; ++c) {
        if (c + 1 < NCH) {
            const float* s = (c + 1 < 8) ? (hsrc + (size_t)(c + 1) * CHUNK * BB) : xsrc;
            prefetch_chunk(hbuf_saddr + ((c + 1) % 3) * (CHUNK * BB * 4), s, tid);
            asm volatile("cp.async.wait_group 1;" ::: "memory");
        } else {
            asm volatile("cp.async.wait_group 0;" ::: "memory");
        }
        __syncthreads();
        const float* hb = hbuf + (size_t)(c % 3) * (CHUNK * BB);
        gate_chunk(hb, W, c * CHUNK, col, bpair, a);
        if (IS_DEC && do_y) {   // y = h_old @ w_out^T row, reusing staged h
            const float* hh = hb + tid;
            const float* wo = wout_s + c * CHUNK;
#pragma unroll 16
            for (int kk = 0; kk < CHUNK; ++kk) yacc += hh[kk * BB] * wo[kk];
        }
    }
    if (IS_DEC && do_y) *yout = yacc + bout_f;

    // elementwise cell update for 2 batch elems, 1 hidden column
    float2 gif0 = unpack2(a.if0), ggo0 = unpack2(a.go0);
    float2 gif1 = unpack2(a.if1), ggo1 = unpack2(a.go1);
    float i0 = sigmoidf(gif0.x), f0 = sigmoidf(gif0.y);
    float g0 = tanhf(ggo0.x),    o0 = sigmoidf(ggo0.y);
    float i1 = sigmoidf(gif1.x), f1 = sigmoidf(gif1.y);
    float g1 = tanhf(ggo1.x),    o1 = sigmoidf(ggo1.y);
    c0 = f0 * c0 + i0 * g0;
    c1 = f1 * c1 + i1 * g1;
    float hv0 = o0 * tanhf(c0);
    float hv1 = o1 * tanhf(c1);
    *(float2*)(hdst + (size_t)j * BB + 2 * bpair) = make_float2(hv0, hv1);

    grid_barrier(s_gen);
}

__global__ void __launch_bounds__(NT, 1) lstm_persistent(
    const float* __restrict__ ts,
    const float* __restrict__ w_ih_enc, const float* __restrict__ w_hh_enc,
    const float* __restrict__ b_ih_enc, const float* __restrict__ b_hh_enc,
    const float* __restrict__ w_ih_dec, const float* __restrict__ w_hh_dec,
    const float* __restrict__ b_ih_dec, const float* __restrict__ b_hh_dec,
    const float* __restrict__ w_out, const float* __restrict__ b_out,
    float* __restrict__ out)
{
    extern __shared__ float smem[];
    float* Wenc   = smem;                              // 576*16 = 9216 floats
    float* Wdec   = Wenc + KENC * 16;                  // 512*16 = 8192
    float* hbuf   = Wdec + HH * 16;                    // 3 * 64*128 = 24576
    float* wout_s = hbuf + 3 * CHUNK * BB;             // 512
    float* bias_e = wout_s + HH;                       // 16
    float* bias_d = bias_e + 16;                       // 16
    __shared__ unsigned int s_gen;

    const int tid = threadIdx.x;
    const int cid = blockIdx.x;
    const int col = tid >> 6;        // 0..3: hidden column within CTA slice
    const int bpair = tid & 63;      // 0..63: pair of batch elements
    const int jb = cid * 4;
    const int j = jb + col;

    if (tid == 0) {
        unsigned int g;
        asm volatile("ld.acquire.gpu.b32 %0, [%1];" : "=r"(g) : "l"(&g_gen) : "memory");
        s_gen = g;
    }

    // --- encoder weights into smem, interleaved [k][col][gate] ---
    for (int idx = tid; idx < KENC * 16; idx += NT) {
        int k = idx >> 4, rem = idx & 15, cc = rem >> 2, g = rem & 3;
        int row = g * HH + jb + cc;
        Wenc[idx] = (k < HH) ? w_hh_enc[(size_t)row * HH + k]
                             : w_ih_enc[(size_t)row * FF + (k - HH)];
    }
    // --- decoder fused weights: W_eff = w_hh_dec + w_ih_dec @ w_out ---
    for (int idx = tid; idx < HH * 16; idx += NT) {
        int k = idx >> 4, rem = idx & 15, cc = rem >> 2, g = rem & 3;
        int row = g * HH + jb + cc;
        float v = w_hh_dec[(size_t)row * HH + k];
        const float* wr = w_ih_dec + (size_t)row * FF;
#pragma unroll 8
        for (int f = 0; f < FF; ++f) v += wr[f] * w_out[(size_t)f * HH + k];
        Wdec[idx] = v;
    }
    // --- biases ---
    if (tid < 16) {
        int cc = tid >> 2, g = tid & 3;
        int row = g * HH + jb + cc;
        bias_e[tid] = b_ih_enc[row] + b_hh_enc[row];
        float v = b_ih_dec[row] + b_hh_dec[row];
        const float* wr = w_ih_dec + (size_t)row * FF;
#pragma unroll 8
        for (int f = 0; f < FF; ++f) v += wr[f] * b_out[f];
        bias_d[tid] = v;
    }
    // --- w_out row for this CTA's output feature (CTAs 0..63) ---
    if (cid < FF) {
        for (int k = tid; k < HH; k += NT) wout_s[k] = w_out[(size_t)cid * HH + k];
    }
    // --- zero initial h (buffer 0) ---
    {
        const int per = (HH * BB) / NB;   // 512 floats per CTA
        for (int i = tid; i < per; i += NT) g_h[0][cid * per + i] = 0.0f;
    }
    // --- transpose input to [t][f][b] for coalesced streaming ---
    for (int tt = 0; tt < TT / NB; ++tt) {
        int t = cid * (TT / NB) + tt;
        for (int idx = tid; idx < FF * BB; idx += NT) {
            int f = idx >> 7, b = idx & (BB - 1);
            g_xT[((size_t)t * FF + f) * BB + b] = ts[((size_t)b * TT + t) * FF + f];
        }
    }
    grid_barrier(&s_gen);

    const unsigned int hbuf_saddr =
        (unsigned int)__cvta_generic_to_shared(hbuf);
    const bool do_y = (cid < FF) && (tid < BB);
    const float bout_f = (cid < FF) ? b_out[cid] : 0.0f;

    float c0 = 0.0f, c1 = 0.0f;

    // ================= encoder: 1024 steps =================
    for (int t = 0; t < TT; ++t) {
        lstm_step<false>(g_h[t & 1], g_h[(t + 1) & 1],
                         g_xT + (size_t)t * FF * BB,
                         Wenc, bias_e, hbuf, hbuf_saddr,
                         nullptr, nullptr, 0.0f, false,
                         tid, col, bpair, j, c0, c1, &s_gen);
    }

    // ================= decoder: 1024 steps (c reset, h carries) =================
    c0 = 0.0f;
    c1 = 0.0f;
    for (int k = 0; k < TT; ++k) {
        // y for (b=tid, f=cid) at output time TT-1-k (only valid when do_y)
        float* yout = out + ((size_t)(tid & (BB - 1)) * TT + (TT - 1 - k)) * FF
                          + (cid & (FF - 1));
        lstm_step<true>(g_h[k & 1], g_h[(k + 1) & 1], nullptr,
                        Wdec, bias_d, hbuf, hbuf_saddr,
                        wout_s, yout, bout_f, do_y,
                        tid, col, bpair, j, c0, c1, &s_gen);
    }
}

// ---------------- launch ----------------
extern "C" void kernel_launch(void* const* d_in, const int* in_sizes, int n_in,
                              void* d_out, int out_size) {
    (void)in_sizes; (void)n_in; (void)out_size;
    const float* ts       = (const float*)d_in[0];
    const float* w_ih_enc = (const float*)d_in[1];
    const float* w_hh_enc = (const float*)d_in[2];
    const float* b_ih_enc = (const float*)d_in[3];
    const float* b_hh_enc = (const float*)d_in[4];
    const float* w_ih_dec = (const float*)d_in[5];
    const float* w_hh_dec = (const float*)d_in[6];
    const float* b_ih_dec = (const float*)d_in[7];
    const float* b_hh_dec = (const float*)d_in[8];
    const float* w_out    = (const float*)d_in[9];
    const float* b_out    = (const float*)d_in[10];
    float* out = (float*)d_out;

    const int smem_bytes = (KENC * 16 + HH * 16 + 3 * CHUNK * BB + HH + 32) * 4;
    static bool attr_set = false;
    if (!attr_set) {
        cudaFuncSetAttribute(lstm_persistent,
                             cudaFuncAttributeMaxDynamicSharedMemorySize, smem_bytes);
        attr_set = true;
    }
    lstm_persistent<<<NB, NT, smem_bytes>>>(
        ts, w_ih_enc, w_hh_enc, b_ih_enc, b_hh_enc,
        b_ih_dec ? w_ih_dec : w_ih_dec, w_hh_dec, b_ih_dec, b_hh_dec, w_out, b_out, out);
}

// round 4
// speedup vs baseline: 1.0446x; 1.0446x over previous
#include <cuda_runtime.h>
#include <cstdint>

#define NB 128      // CTAs (one per SM)
#define NT 512      // threads per CTA: 4 kgroups x 2 colpairs x 64 bpairs
#define BB 128      // batch
#define TT 1024     // seq len
#define FF 64       // features
#define HH 512      // hidden
#define CHUNK 64    // k-chunk staged per pipeline stage (64*128 floats = 32KB)
#define KENC (HH + FF)

typedef unsigned long long ull;

// ---------------- device scratch ----------------
__device__ float g_h[2][HH * BB];      // h double buffer, layout [j][b]
__device__ float g_xT[TT * FF * BB];   // transposed input [t][f][b]
__device__ unsigned int g_flag[8];     // per h-chunk-group ready counters
__device__ unsigned int g_count = 0;   // init barrier
__device__ unsigned int g_gen = 0;

// smem layout (floats)
#define OFF_WENC 0
#define OFF_WDEC 9216
#define OFF_HBUF 17408
#define OFF_WOUT 41984
#define OFF_BE   42496
#define OFF_BD   42512
#define SMEM_FLOATS 42528

// ---------------- packed f32x2 helpers ----------------
__device__ __forceinline__ ull pack2(float x, float y) {
    ull r; asm("mov.b64 %0, {%1, %2};" : "=l"(r) : "f"(x), "f"(y)); return r;
}
__device__ __forceinline__ float2 unpack2(ull v) {
    float2 r; asm("mov.b64 {%0, %1}, %2;" : "=f"(r.x), "=f"(r.y) : "l"(v)); return r;
}
__device__ __forceinline__ void fma2(ull& d, ull a, ull b) {
    asm("fma.rn.f32x2 %0, %1, %2, %0;" : "+l"(d) : "l"(a), "l"(b));
}
__device__ __forceinline__ ull add2(ull a, ull b) {
    ull r; asm("add.rn.f32x2 %0, %1, %2;" : "=l"(r) : "l"(a), "l"(b)); return r;
}
__device__ __forceinline__ float sigf(float x) {
    return __fdividef(1.0f, 1.0f + __expf(-x));
}
__device__ __forceinline__ float tanhfast(float x) {
    return 1.0f - __fdividef(2.0f, __expf(2.0f * x) + 1.0f);
}

// ---------------- init-time grid barrier (monotonic; launch-safe) ----------------
__device__ __forceinline__ void grid_barrier_init() {
    __syncthreads();
    if (threadIdx.x == 0) {
        unsigned int cur0;
        asm volatile("ld.acquire.gpu.b32 %0, [%1];" : "=r"(cur0) : "l"(&g_gen) : "memory");
        unsigned int target = cur0 + 1u;
        __threadfence();
        unsigned int t = atomicAdd(&g_count, 1u);
        if (t == NB - 1u) {
            g_count = 0u;
            asm volatile("st.release.gpu.b32 [%0], %1;" :: "l"(&g_gen), "r"(target) : "memory");
        } else {
            unsigned int cur;
            do {
                __nanosleep(20);
                asm volatile("ld.acquire.gpu.b32 %0, [%1];" : "=r"(cur) : "l"(&g_gen) : "memory");
            } while ((int)(cur - target) < 0);
        }
    }
    __syncthreads();
}

// ---------------- producer-flag spin ----------------
__device__ __forceinline__ void wait_flag(int ch, unsigned int tgt) {
    unsigned int v;
    asm volatile("ld.acquire.gpu.b32 %0, [%1];" : "=r"(v) : "l"(&g_flag[ch]) : "memory");
    while ((int)(v - tgt) < 0) {
        __nanosleep(40);
        asm volatile("ld.acquire.gpu.b32 %0, [%1];" : "=r"(v) : "l"(&g_flag[ch]) : "memory");
    }
}

// ---------------- cp.async: stage one 32KB chunk ----------------
__device__ __forceinline__ void prefetch_chunk(unsigned int smem_dst, const float* src, int tid) {
#pragma unroll
    for (int i = 0; i < 4; i++) {
        int off = tid + NT * i;   // 2048 float4 total
        asm volatile("cp.async.cg.shared.global [%0], [%1], 16;"
                     :: "r"(smem_dst + off * 16), "l"(src + off * 4) : "memory");
    }
    asm volatile("cp.async.commit_group;" ::: "memory");
}

// ---------------- gate GEMM over one staged chunk (this thread's k-quarter) --------
// accs: [colA:(if,b0),(go,b0),(if,b1),(go,b1), colB: same]
template <bool IS_DEC>
__device__ __forceinline__ void consume_chunk(
    const float* hb, const float* Wk, int g, int cp, int bp,
    ull* accs, float& yacc, const float* wo, bool doy, int r)
{
    const float2* hp = (const float2*)hb + (size_t)g * 64 + bp;
    const ulonglong2* wp = (const ulonglong2*)Wk + (size_t)g * 4 + 2 * cp;
#pragma unroll 8
    for (int t = 0; t < 16; ++t) {
        float2 hf = hp[t * 256];           // h pair (b0,b1) at k = g+4t
        ulonglong2 wA = wp[t * 16];        // colA: (wi,wf),(wg,wo)
        ulonglong2 wB = wp[t * 16 + 1];    // colB
        ull hb0 = pack2(hf.x, hf.x);
        ull hb1 = pack2(hf.y, hf.y);
        fma2(accs[0], wA.x, hb0); fma2(accs[1], wA.y, hb0);
        fma2(accs[2], wA.x, hb1); fma2(accs[3], wA.y, hb1);
        fma2(accs[4], wB.x, hb0); fma2(accs[5], wB.y, hb0);
        fma2(accs[6], wB.x, hb1); fma2(accs[7], wB.y, hb1);
    }
    if (IS_DEC && doy) {
#pragma unroll 8
        for (int t = 0; t < 16; ++t)
            yacc += hb[(g + 4 * t) * BB + r] * wo[g + 4 * t];
    }
}

// ---------------- one LSTM step ----------------
template <bool IS_DEC>
__device__ __forceinline__ void do_step(
    int s, int gidx, const float* hsrc, float* hdst, const float* xsrc,
    const float* W, const float* bias_s, float* hbuf, unsigned int hbuf_sa,
    const float* wout_s, float* yout, float bout, bool doy,
    int tid, int g, int cp, int bp, int r, int jb,
    float& c0, float& c1, float& c2, float& c3)
{
    const int NC = IS_DEC ? 8 : 9;
    const unsigned int tgt = 16u * (unsigned)(s + 1);

    ull accs[8];
    if (g == 0) {
        const ull* bA = (const ull*)bias_s + 4 * cp;     // colA: (bi,bf),(bg,bo)
        accs[0] = bA[0]; accs[1] = bA[1];
        accs[2] = bA[0]; accs[3] = bA[1];
        accs[4] = bA[2]; accs[5] = bA[3];                // colB
        accs[6] = bA[2]; accs[7] = bA[3];
    } else {
#pragma unroll
        for (int q = 0; q < 8; ++q) accs[q] = 0ull;
    }
    float yacc = 0.0f;

    // stage first chunk (own group's — usually flag already satisfied)
    {
        int ch = gidx;
        wait_flag(ch, tgt);
        prefetch_chunk(hbuf_sa, hsrc + (size_t)ch * (CHUNK * BB), tid);
    }
    for (int i = 0; i < NC; ++i) {
        if (i + 1 < NC) {
            const float* src;
            if (!IS_DEC && i + 1 == 8) {
                src = xsrc;                               // x chunk: no flag
            } else {
                int ch = (gidx + i + 1) & 7;
                wait_flag(ch, tgt);
                src = hsrc + (size_t)ch * (CHUNK * BB);
            }
            prefetch_chunk(hbuf_sa + ((i + 1) % 3) * (CHUNK * BB * 4), src, tid);
            asm volatile("cp.async.wait_group 1;" ::: "memory");
        } else {
            asm volatile("cp.async.wait_group 0;" ::: "memory");
        }
        __syncthreads();
        const float* hb = hbuf + (size_t)(i % 3) * (CHUNK * BB);
        int wk = (!IS_DEC && i == 8) ? HH : ((gidx + i) & 7) * CHUNK;
        consume_chunk<IS_DEC>(hb, W + (size_t)wk * 16, g, cp, bp,
                              accs, yacc, wout_s + wk, doy, r);
    }

    // ---- cross-kgroup reduction through smem (aliased onto hbuf buffer 0) ----
    __syncthreads();
    ull* red = (ull*)hbuf;                  // 384 threads x 8 ull = 24KB (< buf0)
    float* red_y = hbuf + 6144;             // 384 floats
    if (g > 0) {
        ull* p = red + ((size_t)(g - 1) * 128 + r) * 8;
#pragma unroll
        for (int q = 0; q < 8; ++q) p[q] = accs[q];
        if (IS_DEC && doy) red_y[(g - 1) * 128 + r] = yacc;
    }
    __syncthreads();
    if (g == 0) {
#pragma unroll
        for (int gg = 0; gg < 3; ++gg) {
            const ull* p = red + ((size_t)gg * 128 + r) * 8;
#pragma unroll
            for (int q = 0; q < 8; ++q) accs[q] = add2(accs[q], p[q]);
        }
        // activations + cell update for 4 outputs (2 cols x 2 batch)
        float2 ifA0 = unpack2(accs[0]), goA0 = unpack2(accs[1]);
        float2 ifA1 = unpack2(accs[2]), goA1 = unpack2(accs[3]);
        float2 ifB0 = unpack2(accs[4]), goB0 = unpack2(accs[5]);
        float2 ifB1 = unpack2(accs[6]), goB1 = unpack2(accs[7]);
        c0 = sigf(ifA0.y) * c0 + sigf(ifA0.x) * tanhfast(goA0.x);
        c1 = sigf(ifA1.y) * c1 + sigf(ifA1.x) * tanhfast(goA1.x);
        c2 = sigf(ifB0.y) * c2 + sigf(ifB0.x) * tanhfast(goB0.x);
        c3 = sigf(ifB1.y) * c3 + sigf(ifB1.x) * tanhfast(goB1.x);
        float hA0 = sigf(goA0.y) * tanhfast(c0);
        float hA1 = sigf(goA1.y) * tanhfast(c1);
        float hB0 = sigf(goB0.y) * tanhfast(c2);
        float hB1 = sigf(goB1.y) * tanhfast(c3);
        *(float2*)(hdst + (size_t)(jb + 2 * cp) * BB + 2 * bp)     = make_float2(hA0, hA1);
        *(float2*)(hdst + (size_t)(jb + 2 * cp + 1) * BB + 2 * bp) = make_float2(hB0, hB1);
        if (IS_DEC && doy) {
            float y = yacc + red_y[r] + red_y[128 + r] + red_y[256 + r] + bout;
            *yout = y;
        }
    }
    __syncthreads();   // epilogue done (protects red region + h STGs) before flag/next stage
    if (tid == 0) {
        __threadfence();
        atomicAdd(&g_flag[gidx], 1u);    // release: h_{s+1} slice ready
    }
}

__global__ void reset_flags_kernel() {
    if (threadIdx.x < 8) g_flag[threadIdx.x] = 16u;   // h_0 "ready" baseline
}

__global__ void __launch_bounds__(NT, 1) lstm_persistent(
    const float* __restrict__ ts,
    const float* __restrict__ w_ih_enc, const float* __restrict__ w_hh_enc,
    const float* __restrict__ b_ih_enc, const float* __restrict__ b_hh_enc,
    const float* __restrict__ w_ih_dec, const float* __restrict__ w_hh_dec,
    const float* __restrict__ b_ih_dec, const float* __restrict__ b_hh_dec,
    const float* __restrict__ w_out, const float* __restrict__ b_out,
    float* __restrict__ out)
{
    extern __shared__ float smem[];
    float* Wenc   = smem + OFF_WENC;
    float* Wdec   = smem + OFF_WDEC;
    float* hbuf   = smem + OFF_HBUF;
    float* wout_s = smem + OFF_WOUT;
    float* bias_e = smem + OFF_BE;
    float* bias_d = smem + OFF_BD;

    const int tid = threadIdx.x;
    const int cid = blockIdx.x;
    const int g   = tid >> 7;         // kgroup 0..3
    const int r   = tid & 127;        // 0..127 (also batch index for y)
    const int cp  = r >> 6;           // colpair 0..1
    const int bp  = r & 63;           // batch pair 0..63
    const int jb  = cid * 4;
    const int gidx = cid >> 4;        // h-chunk group this CTA produces

    // --- encoder weights into smem: layout [k][col(4)][gate(4)] ---
    for (int idx = tid; idx < KENC * 16; idx += NT) {
        int k = idx >> 4, rem = idx & 15, cc = rem >> 2, q = rem & 3;
        int row = q * HH + jb + cc;
        Wenc[idx] = (k < HH) ? w_hh_enc[(size_t)row * HH + k]
                             : w_ih_enc[(size_t)row * FF + (k - HH)];
    }
    // --- decoder fused weights: W_eff = w_hh_dec + w_ih_dec @ w_out ---
    for (int idx = tid; idx < HH * 16; idx += NT) {
        int k = idx >> 4, rem = idx & 15, cc = rem >> 2, q = rem & 3;
        int row = q * HH + jb + cc;
        float v = w_hh_dec[(size_t)row * HH + k];
        const float* wr = w_ih_dec + (size_t)row * FF;
#pragma unroll 8
        for (int f = 0; f < FF; ++f) v += wr[f] * w_out[(size_t)f * HH + k];
        Wdec[idx] = v;
    }
    // --- biases: layout [col][gate] ---
    if (tid < 16) {
        int cc = tid >> 2, q = tid & 3;
        int row = q * HH + jb + cc;
        bias_e[tid] = b_ih_enc[row] + b_hh_enc[row];
        float v = b_ih_dec[row] + b_hh_dec[row];
        const float* wr = w_ih_dec + (size_t)row * FF;
#pragma unroll 8
        for (int f = 0; f < FF; ++f) v += wr[f] * b_out[f];
        bias_d[tid] = v;
    }
    // --- w_out row for this CTA's output feature ---
    if (cid < FF) {
        for (int k = tid; k < HH; k += NT) wout_s[k] = w_out[(size_t)cid * HH + k];
    }
    // --- zero own h_0 slice ---
    for (int i = tid; i < 512; i += NT) g_h[0][(size_t)cid * 512 + i] = 0.0f;
    // --- transpose input to [t][f][b] ---
    for (int tt = 0; tt < TT / NB; ++tt) {
        int t = cid * (TT / NB) + tt;
        for (int idx = tid; idx < FF * BB; idx += NT) {
            int f = idx >> 7, b = idx & (BB - 1);
            g_xT[((size_t)t * FF + f) * BB + b] = ts[((size_t)b * TT + t) * FF + f];
        }
    }
    grid_barrier_init();

    const unsigned int hbuf_sa = (unsigned int)__cvta_generic_to_shared(hbuf);
    const bool doy = (cid < FF);
    const float bout = doy ? b_out[cid] : 0.0f;

    float c0 = 0.0f, c1 = 0.0f, c2 = 0.0f, c3 = 0.0f;

    // ================= encoder: 1024 steps =================
    for (int s = 0; s < TT; ++s) {
        do_step<false>(s, gidx, g_h[s & 1], g_h[(s + 1) & 1],
                       g_xT + (size_t)s * FF * BB,
                       Wenc, bias_e, hbuf, hbuf_sa,
                       wout_s, nullptr, 0.0f, false,
                       tid, g, cp, bp, r, jb, c0, c1, c2, c3);
    }
    // ================= decoder: 1024 steps (c reset, h carries) =================
    c0 = c1 = c2 = c3 = 0.0f;
    for (int kd = 0; kd < TT; ++kd) {
        int s = TT + kd;
        float* yout = out + ((size_t)r * TT + (TT - 1 - kd)) * FF + (cid & (FF - 1));
        do_step<true>(s, gidx, g_h[s & 1], g_h[(s + 1) & 1], nullptr,
                      Wdec, bias_d, hbuf, hbuf_sa,
                      wout_s, yout, bout, doy,
                      tid, g, cp, bp, r, jb, c0, c1, c2, c3);
    }
}

// ---------------- launch ----------------
extern "C" void kernel_launch(void* const* d_in, const int* in_sizes, int n_in,
                              void* d_out, int out_size) {
    (void)in_sizes; (void)n_in; (void)out_size;
    const float* ts       = (const float*)d_in[0];
    const float* w_ih_enc = (const float*)d_in[1];
    const float* w_hh_enc = (const float*)d_in[2];
    const float* b_ih_enc = (const float*)d_in[3];
    const float* b_hh_enc = (const float*)d_in[4];
    const float* w_ih_dec = (const float*)d_in[5];
    const float* w_hh_dec = (const float*)d_in[6];
    const float* b_ih_dec = (const float*)d_in[7];
    const float* b_hh_dec = (const float*)d_in[8];
    const float* w_out    = (const float*)d_in[9];
    const float* b_out    = (const float*)d_in[10];
    float* out = (float*)d_out;

    const int smem_bytes = SMEM_FLOATS * 4;   // ~166KB
    static bool attr_set = false;
    if (!attr_set) {
        cudaFuncSetAttribute(lstm_persistent,
                             cudaFuncAttributeMaxDynamicSharedMemorySize, smem_bytes);
        attr_set = true;
    }
    reset_flags_kernel<<<1, 32>>>();
    lstm_persistent<<<NB, NT, smem_bytes>>>(
        ts, w_ih_enc, w_hh_enc, b_ih_enc, b_hh_enc,
        w_ih_dec, w_hh_dec, b_ih_dec, b_hh_dec, w_out, b_out, out);
}

// round 5
// speedup vs baseline: 1.6483x; 1.5780x over previous
#include <cuda_runtime.h>
#include <cstdint>

#define NB 128      // CTAs (one per SM)
#define NT 512      // threads: 8 kgroups x 64 (2 colpairs x 32 bquads)
#define BB 128      // batch
#define TT 1024     // seq len
#define FF 64       // features
#define HH 512      // hidden
#define CHUNK 64    // k-chunk staged per stage (32KB)
#define KENC (HH + FF)

typedef unsigned long long ull;

// ---------------- device scratch ----------------
__device__ float g_h[2][HH * BB];      // h double buffer [j][b]
__device__ float g_xT[TT * FF * BB];   // transposed input [t][f][b]
__device__ unsigned int g_flag[8];     // per h-chunk-group ready counters
__device__ unsigned int g_count = 0;
__device__ unsigned int g_gen = 0;

// smem layout (floats)
#define OFF_WENC 0
#define OFF_WDEC 9216
#define OFF_HBUF 17408          // 3 stages x 8192 floats = 24576
#define OFF_WOUT 41984
#define OFF_BE   42496
#define OFF_BD   42512
#define SMEM_FLOATS 42528
// reduction region aliases hbuf: red = 512 slots x 18 ull (144B padded) = 18432 floats
#define RED_Y_OFF 18432          // floats into hbuf; 8*128 = 1024 floats

__device__ __forceinline__ ull pack2(float x, float y) {
    ull r; asm("mov.b64 %0, {%1, %2};" : "=l"(r) : "f"(x), "f"(y)); return r;
}
__device__ __forceinline__ float2 unpack2(ull v) {
    float2 r; asm("mov.b64 {%0, %1}, %2;" : "=f"(r.x), "=f"(r.y) : "l"(v)); return r;
}
__device__ __forceinline__ void fma2(ull& d, ull a, ull b) {
    asm("fma.rn.f32x2 %0, %1, %2, %0;" : "+l"(d) : "l"(a), "l"(b));
}
__device__ __forceinline__ ull add2(ull a, ull b) {
    ull r; asm("add.rn.f32x2 %0, %1, %2;" : "=l"(r) : "l"(a), "l"(b)); return r;
}
__device__ __forceinline__ float sigf(float x) {
    return __fdividef(1.0f, 1.0f + __expf(-x));
}
__device__ __forceinline__ float tanhfast(float x) {
    return 1.0f - __fdividef(2.0f, __expf(2.0f * x) + 1.0f);
}

__device__ __forceinline__ void grid_barrier_init() {
    __syncthreads();
    if (threadIdx.x == 0) {
        unsigned int cur0;
        asm volatile("ld.acquire.gpu.b32 %0, [%1];" : "=r"(cur0) : "l"(&g_gen) : "memory");
        unsigned int target = cur0 + 1u;
        __threadfence();
        unsigned int t = atomicAdd(&g_count, 1u);
        if (t == NB - 1u) {
            g_count = 0u;
            asm volatile("st.release.gpu.b32 [%0], %1;" :: "l"(&g_gen), "r"(target) : "memory");
        } else {
            unsigned int cur;
            do {
                __nanosleep(20);
                asm volatile("ld.acquire.gpu.b32 %0, [%1];" : "=r"(cur) : "l"(&g_gen) : "memory");
            } while ((int)(cur - target) < 0);
        }
    }
    __syncthreads();
}

__device__ __forceinline__ void wait_flag(int ch, unsigned int tgt) {
    unsigned int v;
    asm volatile("ld.acquire.gpu.b32 %0, [%1];" : "=r"(v) : "l"(&g_flag[ch]) : "memory");
    while ((int)(v - tgt) < 0) {
        __nanosleep(32);
        asm volatile("ld.acquire.gpu.b32 %0, [%1];" : "=r"(v) : "l"(&g_flag[ch]) : "memory");
    }
}

__device__ __forceinline__ void prefetch_chunk(unsigned int smem_dst, const float* src, int tid) {
#pragma unroll
    for (int i = 0; i < 4; i++) {
        int off = tid + NT * i;   // 2048 float4
        asm volatile("cp.async.cg.shared.global [%0], [%1], 16;"
                     :: "r"(smem_dst + off * 16), "l"(src + off * 4) : "memory");
    }
    asm volatile("cp.async.commit_group;" ::: "memory");
}

// consume one staged chunk, this thread's k-eighth (8 k values, stride 8)
// acc[colX*8 + bidx*2 + gp] : ull=(i,f) or (g,o) partial for (col 2cp+colX, b 4rb+bidx)
template <bool IS_DEC>
__device__ __forceinline__ void consume_chunk(
    const float* hb, const float* Wk, const float* wo,
    int g, int cp, int rb, ull* acc, bool doy, ull& y01, ull& y23)
{
    const float4* hp = (const float4*)hb + (g * 32 + rb);      // k=g, b=4rb
    const ull* wp = (const ull*)Wk + (g * 8 + cp * 4);         // cols 2cp,2cp+1
#pragma unroll
    for (int t = 0; t < 8; ++t) {
        float4 h4 = hp[t * 256];                 // k = g + 8t
        ull wif0 = wp[t * 64 + 0], wgo0 = wp[t * 64 + 1];
        ull wif1 = wp[t * 64 + 2], wgo1 = wp[t * 64 + 3];
        ull h0 = pack2(h4.x, h4.x), h1 = pack2(h4.y, h4.y);
        ull h2 = pack2(h4.z, h4.z), h3 = pack2(h4.w, h4.w);
        fma2(acc[0],  wif0, h0); fma2(acc[1],  wgo0, h0);
        fma2(acc[2],  wif0, h1); fma2(acc[3],  wgo0, h1);
        fma2(acc[4],  wif0, h2); fma2(acc[5],  wgo0, h2);
        fma2(acc[6],  wif0, h3); fma2(acc[7],  wgo0, h3);
        fma2(acc[8],  wif1, h0); fma2(acc[9],  wgo1, h0);
        fma2(acc[10], wif1, h1); fma2(acc[11], wgo1, h1);
        fma2(acc[12], wif1, h2); fma2(acc[13], wgo1, h2);
        fma2(acc[14], wif1, h3); fma2(acc[15], wgo1, h3);
        if (IS_DEC && doy) {
            float w = wo[g + 8 * t];
            ull ws = pack2(w, w);
            fma2(y01, ws, ((const ull*)&h4)[0]);
            fma2(y23, ws, ((const ull*)&h4)[1]);
        }
    }
}

// one LSTM step
template <bool IS_DEC>
__device__ __forceinline__ void do_step(
    int s, int kd, int gidx, const float* hsrc, float* hdst, const float* xsrc,
    const float* W, const float* bias_s, float* hbuf, unsigned int hbuf_sa,
    const float* wout_s, float* out, int cid, float bout, bool doy,
    int tid, int g, int cp, int rb, int col, int b, int jb, float& cst)
{
    const int NC = IS_DEC ? 8 : 9;
    const unsigned int tgt = 16u * (unsigned)(s + 1);

    // parallel upfront wait for all 8 producer flags
    if (tid < 8) wait_flag(tid, tgt);
    __syncthreads();

    ull acc[16];
#pragma unroll
    for (int q = 0; q < 16; ++q) acc[q] = 0ull;
    ull y01 = 0ull, y23 = 0ull;

    // depth-2 pipeline: prologue stages chunks 0,1
    prefetch_chunk(hbuf_sa, hsrc, tid);
    prefetch_chunk(hbuf_sa + 32768u, hsrc + CHUNK * BB, tid);

    for (int i = 0; i < NC; ++i) {
        if (i + 2 < NC) {
            const float* src = (!IS_DEC && i + 2 == 8) ? xsrc
                               : hsrc + (size_t)(i + 2) * (CHUNK * BB);
            prefetch_chunk(hbuf_sa + (unsigned)((i + 2) % 3) * 32768u, src, tid);
            asm volatile("cp.async.wait_group 2;" ::: "memory");
        } else if (i + 1 < NC) {
            asm volatile("cp.async.wait_group 1;" ::: "memory");
        } else {
            asm volatile("cp.async.wait_group 0;" ::: "memory");
        }
        __syncthreads();
        const float* hb = hbuf + (size_t)(i % 3) * (CHUNK * BB);
        consume_chunk<IS_DEC>(hb, W + (size_t)i * CHUNK * 16, wout_s + i * CHUNK,
                              g, cp, rb, acc, doy, y01, y23);
    }

    // ---- reduction: all threads store partials, all threads reduce one cell ----
    __syncthreads();
    ull* red = (ull*)hbuf;                      // 512 slots x 18 ull (padded)
    float* ry = hbuf + RED_Y_OFF;
    {
        ull* myp = red + (size_t)(g * 64 + (cp * 32 + rb)) * 18;
#pragma unroll
        for (int q = 0; q < 16; q += 2)
            *(ulonglong2*)(myp + q) = make_ulonglong2(acc[q], acc[q + 1]);
        if (IS_DEC && doy && cp == 0) {
            float2 ya = unpack2(y01), yb = unpack2(y23);
            *(float4*)(ry + g * BB + 4 * rb) = make_float4(ya.x, ya.y, yb.x, yb.y);
        }
    }
    __syncthreads();
    {
        int col1 = col & 1;
        int r_o = (col >> 1) * 32 + (b >> 2);
        int jj = col1 * 8 + (b & 3) * 2;
        ull aif = ((const ull*)bias_s)[col * 2];
        ull ago = ((const ull*)bias_s)[col * 2 + 1];
#pragma unroll
        for (int gg = 0; gg < 8; ++gg) {
            ulonglong2 p = *(const ulonglong2*)(red + (size_t)(gg * 64 + r_o) * 18 + jj);
            aif = add2(aif, p.x);
            ago = add2(ago, p.y);
        }
        float2 sif = unpack2(aif), sgo = unpack2(ago);
        float iv = sigf(sif.x), fv = sigf(sif.y);
        float gv = tanhfast(sgo.x), ov = sigf(sgo.y);
        cst = fv * cst + iv * gv;
        float hv = ov * tanhfast(cst);
        hdst[(size_t)(jb + col) * BB + b] = hv;
        if (IS_DEC && doy && col == 0) {
            float y = bout;
#pragma unroll
            for (int gg = 0; gg < 8; ++gg) y += ry[gg * BB + b];
            out[((size_t)b * TT + (TT - 1 - kd)) * FF + cid] = y;
        }
    }
    __syncthreads();
    if (tid == 0) {
        __threadfence();
        atomicAdd(&g_flag[gidx], 1u);
    }
}

__global__ void reset_flags_kernel() {
    if (threadIdx.x < 8) g_flag[threadIdx.x] = 16u;
}

__global__ void __launch_bounds__(NT, 1) lstm_persistent(
    const float* __restrict__ ts,
    const float* __restrict__ w_ih_enc, const float* __restrict__ w_hh_enc,
    const float* __restrict__ b_ih_enc, const float* __restrict__ b_hh_enc,
    const float* __restrict__ w_ih_dec, const float* __restrict__ w_hh_dec,
    const float* __restrict__ b_ih_dec, const float* __restrict__ b_hh_dec,
    const float* __restrict__ w_out, const float* __restrict__ b_out,
    float* __restrict__ out)
{
    extern __shared__ float smem[];
    float* Wenc   = smem + OFF_WENC;
    float* Wdec   = smem + OFF_WDEC;
    float* hbuf   = smem + OFF_HBUF;
    float* wout_s = smem + OFF_WOUT;
    float* bias_e = smem + OFF_BE;
    float* bias_d = smem + OFF_BD;

    const int tid = threadIdx.x;
    const int cid = blockIdx.x;
    const int g   = tid >> 6;        // kgroup 0..7
    const int r   = tid & 63;
    const int cp  = r >> 5;          // colpair 0..1 (cols 2cp, 2cp+1)
    const int rb  = r & 31;          // batch quad index (b = 4rb..4rb+3)
    const int col = tid >> 7;        // epilogue mapping: col 0..3
    const int b   = tid & 127;       // epilogue mapping: batch 0..127
    const int jb  = cid * 4;
    const int gidx = cid >> 4;       // h-chunk group this CTA produces

    // --- encoder weights: layout [k][col(4)][gate(4)] ---
    for (int idx = tid; idx < KENC * 16; idx += NT) {
        int k = idx >> 4, rem = idx & 15, cc = rem >> 2, q = rem & 3;
        int row = q * HH + jb + cc;
        Wenc[idx] = (k < HH) ? w_hh_enc[(size_t)row * HH + k]
                             : w_ih_enc[(size_t)row * FF + (k - HH)];
    }
    // --- decoder fused weights: W_eff = w_hh_dec + w_ih_dec @ w_out ---
    for (int idx = tid; idx < HH * 16; idx += NT) {
        int k = idx >> 4, rem = idx & 15, cc = rem >> 2, q = rem & 3;
        int row = q * HH + jb + cc;
        float v = w_hh_dec[(size_t)row * HH + k];
        const float* wr = w_ih_dec + (size_t)row * FF;
#pragma unroll 8
        for (int f = 0; f < FF; ++f) v += wr[f] * w_out[(size_t)f * HH + k];
        Wdec[idx] = v;
    }
    // --- biases: layout [col][gate] ---
    if (tid < 16) {
        int cc = tid >> 2, q = tid & 3;
        int row = q * HH + jb + cc;
        bias_e[tid] = b_ih_enc[row] + b_hh_enc[row];
        float v = b_ih_dec[row] + b_hh_dec[row];
        const float* wr = w_ih_dec + (size_t)row * FF;
#pragma unroll 8
        for (int f = 0; f < FF; ++f) v += wr[f] * b_out[f];
        bias_d[tid] = v;
    }
    if (cid < FF) {
        for (int k = tid; k < HH; k += NT) wout_s[k] = w_out[(size_t)cid * HH + k];
    }
    for (int i = tid; i < 512; i += NT) g_h[0][(size_t)cid * 512 + i] = 0.0f;
    for (int tt = 0; tt < TT / NB; ++tt) {
        int t = cid * (TT / NB) + tt;
        for (int idx = tid; idx < FF * BB; idx += NT) {
            int f = idx >> 7, bb = idx & (BB - 1);
            g_xT[((size_t)t * FF + f) * BB + bb] = ts[((size_t)bb * TT + t) * FF + f];
        }
    }
    grid_barrier_init();

    const unsigned int hbuf_sa = (unsigned int)__cvta_generic_to_shared(hbuf);
    const bool doy = (cid < FF);
    const float bout = doy ? b_out[cid] : 0.0f;

    float cst = 0.0f;

    // ================= encoder =================
    for (int s = 0; s < TT; ++s) {
        do_step<false>(s, 0, gidx, g_h[s & 1], g_h[(s + 1) & 1],
                       g_xT + (size_t)s * FF * BB,
                       Wenc, bias_e, hbuf, hbuf_sa,
                       wout_s, nullptr, cid, 0.0f, false,
                       tid, g, cp, rb, col, b, jb, cst);
    }
    // ================= decoder =================
    cst = 0.0f;
    for (int kd = 0; kd < TT; ++kd) {
        int s = TT + kd;
        do_step<true>(s, kd, gidx, g_h[s & 1], g_h[(s + 1) & 1], nullptr,
                      Wdec, bias_d, hbuf, hbuf_sa,
                      wout_s, out, cid, bout, doy,
                      tid, g, cp, rb, col, b, jb, cst);
    }
}

extern "C" void kernel_launch(void* const* d_in, const int* in_sizes, int n_in,
                              void* d_out, int out_size) {
    (void)in_sizes; (void)n_in; (void)out_size;
    const float* ts       = (const float*)d_in[0];
    const float* w_ih_enc = (const float*)d_in[1];
    const float* w_hh_enc = (const float*)d_in[2];
    const float* b_ih_enc = (const float*)d_in[3];
    const float* b_hh_enc = (const float*)d_in[4];
    const float* w_ih_dec = (const float*)d_in[5];
    const float* w_hh_dec = (const float*)d_in[6];
    const float* b_ih_dec = (const float*)d_in[7];
    const float* b_hh_dec = (const float*)d_in[8];
    const float* w_out    = (const float*)d_in[9];
    const float* b_out    = (const float*)d_in[10];
    float* out = (float*)d_out;

    const int smem_bytes = SMEM_FLOATS * 4;
    static bool attr_set = false;
    if (!attr_set) {
        cudaFuncSetAttribute(lstm_persistent,
                             cudaFuncAttributeMaxDynamicSharedMemorySize, smem_bytes);
        attr_set = true;
    }
    reset_flags_kernel<<<1, 32>>>();
    lstm_persistent<<<NB, NT, smem_bytes>>>(
        ts, w_ih_enc, w_hh_enc, b_ih_enc, b_hh_enc,
        w_ih_dec, w_hh_dec, b_ih_dec, b_hh_dec, w_out, b_out, out);
}

// round 6
// speedup vs baseline: 1.6581x; 1.0060x over previous
#include <cuda_runtime.h>
#include <cstdint>

#define NB 128      // CTAs (one per SM)
#define NT 512      // threads: 8 kgroups x 64 (2 colpairs x 32 bquads)
#define BB 128      // batch
#define TT 1024     // seq len
#define FF 64       // features
#define HH 512      // hidden
#define CHUNK 64    // k-chunk per stage (8192 floats = 32KB)
#define KENC (HH + FF)

typedef unsigned long long ull;

// ---------------- device scratch ----------------
__device__ float g_h[2][HH * BB];      // h double buffer [j][b]
__device__ float g_xT[TT * FF * BB];   // transposed input [t][f][b]
__device__ unsigned int g_flag[8];     // per h-chunk-group ready counters
__device__ unsigned int g_count = 0;
__device__ unsigned int g_gen = 0;

// smem layout (float offsets)
#define OFF_WENC 0               // 9216
#define OFF_WDEC 9216            // 8192
#define OFF_HBUF 17408           // 2 stages x 8192 = 16384
#define OFF_RED  33792           // 512 slots x 18 ull = 18432 floats (dedicated!)
#define OFF_RY   52224           // 1024
#define OFF_WOUT 53248           // 512
#define OFF_BE   53760           // 16
#define OFF_BD   53776           // 16
#define OFF_MBAR 53792           // 4 mbarriers x 8B = 8 floats (8B aligned)
#define SMEM_FLOATS 53800        // ~210.2 KB

__device__ __forceinline__ ull pack2(float x, float y) {
    ull r; asm("mov.b64 %0, {%1, %2};" : "=l"(r) : "f"(x), "f"(y)); return r;
}
__device__ __forceinline__ float2 unpack2(ull v) {
    float2 r; asm("mov.b64 {%0, %1}, %2;" : "=f"(r.x), "=f"(r.y) : "l"(v)); return r;
}
__device__ __forceinline__ void fma2(ull& d, ull a, ull b) {
    asm("fma.rn.f32x2 %0, %1, %2, %0;" : "+l"(d) : "l"(a), "l"(b));
}
__device__ __forceinline__ ull add2(ull a, ull b) {
    ull r; asm("add.rn.f32x2 %0, %1, %2;" : "=l"(r) : "l"(a), "l"(b)); return r;
}
__device__ __forceinline__ float sigf(float x) {
    return __fdividef(1.0f, 1.0f + __expf(-x));
}
__device__ __forceinline__ float tanhfast(float x) {
    return 1.0f - __fdividef(2.0f, __expf(2.0f * x) + 1.0f);
}

// ---------------- mbarrier primitives ----------------
__device__ __forceinline__ void mbar_init(uint32_t a, uint32_t cnt) {
    asm volatile("mbarrier.init.shared.b64 [%0], %1;" :: "r"(a), "r"(cnt) : "memory");
}
__device__ __forceinline__ void mbar_arrive(uint32_t a) {
    asm volatile("mbarrier.arrive.shared.b64 _, [%0];" :: "r"(a) : "memory");
}
__device__ __forceinline__ void cp_arrive(uint32_t a) {
    asm volatile("cp.async.mbarrier.arrive.noinc.shared.b64 [%0];" :: "r"(a) : "memory");
}
__device__ __forceinline__ void mbar_wait(uint32_t a, uint32_t parity) {
    asm volatile(
        "{\n\t.reg .pred P;\n"
        "WL_%=:\n\t"
        "mbarrier.try_wait.parity.shared.b64 P, [%0], %1, 0x989680;\n\t"
        "@P bra WD_%=;\n\t"
        "bra WL_%=;\n"
        "WD_%=:\n\t}"
        :: "r"(a), "r"(parity) : "memory");
}

__device__ __forceinline__ void grid_barrier_init() {
    __syncthreads();
    if (threadIdx.x == 0) {
        unsigned int cur0;
        asm volatile("ld.acquire.gpu.b32 %0, [%1];" : "=r"(cur0) : "l"(&g_gen) : "memory");
        unsigned int target = cur0 + 1u;
        __threadfence();
        unsigned int t = atomicAdd(&g_count, 1u);
        if (t == NB - 1u) {
            g_count = 0u;
            asm volatile("st.release.gpu.b32 [%0], %1;" :: "l"(&g_gen), "r"(target) : "memory");
        } else {
            unsigned int cur;
            do {
                __nanosleep(20);
                asm volatile("ld.acquire.gpu.b32 %0, [%1];" : "=r"(cur) : "l"(&g_gen) : "memory");
            } while ((int)(cur - target) < 0);
        }
    }
    __syncthreads();
}

__device__ __forceinline__ void wait_flag(int ch, unsigned int tgt) {
    unsigned int v;
    asm volatile("ld.acquire.gpu.b32 %0, [%1];" : "=r"(v) : "l"(&g_flag[ch]) : "memory");
    while ((int)(v - tgt) < 0) {
        __nanosleep(32);
        asm volatile("ld.acquire.gpu.b32 %0, [%1];" : "=r"(v) : "l"(&g_flag[ch]) : "memory");
    }
}

// stage one 32KB chunk: 4 cp.async per thread, then bind to full mbarrier
__device__ __forceinline__ void prefetch_chunk(unsigned int smem_dst, const float* src,
                                               int tid, uint32_t mb_full) {
#pragma unroll
    for (int i = 0; i < 4; i++) {
        int off = tid + NT * i;   // 2048 float4
        asm volatile("cp.async.cg.shared.global [%0], [%1], 16;"
                     :: "r"(smem_dst + off * 16), "l"(src + off * 4) : "memory");
    }
    cp_arrive(mb_full);
}

// consume one staged chunk, this thread's k-eighth (8 k values, stride 8)
template <bool IS_DEC>
__device__ __forceinline__ void consume_chunk(
    const float* hb, const float* Wk, const float* wo,
    int g, int cp, int rb, ull* acc, bool doy, ull& y01, ull& y23)
{
    const float4* hp = (const float4*)hb + (g * 32 + rb);
    const ull* wp = (const ull*)Wk + (g * 8 + cp * 4);
#pragma unroll
    for (int t = 0; t < 8; ++t) {
        float4 h4 = hp[t * 256];
        ull wif0 = wp[t * 64 + 0], wgo0 = wp[t * 64 + 1];
        ull wif1 = wp[t * 64 + 2], wgo1 = wp[t * 64 + 3];
        ull h0 = pack2(h4.x, h4.x), h1 = pack2(h4.y, h4.y);
        ull h2 = pack2(h4.z, h4.z), h3 = pack2(h4.w, h4.w);
        fma2(acc[0],  wif0, h0); fma2(acc[1],  wgo0, h0);
        fma2(acc[2],  wif0, h1); fma2(acc[3],  wgo0, h1);
        fma2(acc[4],  wif0, h2); fma2(acc[5],  wgo0, h2);
        fma2(acc[6],  wif0, h3); fma2(acc[7],  wgo0, h3);
        fma2(acc[8],  wif1, h0); fma2(acc[9],  wgo1, h0);
        fma2(acc[10], wif1, h1); fma2(acc[11], wgo1, h1);
        fma2(acc[12], wif1, h2); fma2(acc[13], wgo1, h2);
        fma2(acc[14], wif1, h3); fma2(acc[15], wgo1, h3);
        if (IS_DEC && doy) {
            float w = wo[g + 8 * t];
            ull ws = pack2(w, w);
            fma2(y01, ws, ((const ull*)&h4)[0]);
            fma2(y23, ws, ((const ull*)&h4)[1]);
        }
    }
}

struct PipeState {
    uint32_t full[2], empty[2];
    int fcnt[2], ecnt[2];
};

// one LSTM step
template <bool IS_DEC>
__device__ __forceinline__ void do_step(
    int s, int kd, int gidx, const float* hsrc, float* hdst, const float* xsrc,
    const float* W, const float* bias_s, float* smem, unsigned int hbuf_sa,
    const float* wout_s, float* out, int cid, float bout, bool doy,
    int tid, int g, int cp, int rb, int col, int b, int jb, float& cst,
    PipeState& ps)
{
    const int NC = IS_DEC ? 8 : 9;
    const unsigned int tgt = 16u * (unsigned)(s + 1);
    float* hbuf = smem + OFF_HBUF;

    if (tid < 8) wait_flag(tid, tgt);
    __syncthreads();

    ull acc[16];
#pragma unroll
    for (int q = 0; q < 16; ++q) acc[q] = 0ull;
    ull y01 = 0ull, y23 = 0ull;

    // prologue: stage chunk 0
    mbar_wait(ps.empty[0], (uint32_t)(ps.ecnt[0] & 1)); ps.ecnt[0]++;
    prefetch_chunk(hbuf_sa, hsrc, tid, ps.full[0]);

    for (int i = 0; i < NC; ++i) {
        int st = i & 1;
        if (i + 1 < NC) {
            int st1 = st ^ 1;
            const float* src = (!IS_DEC && i + 1 == 8) ? xsrc
                               : hsrc + (size_t)(i + 1) * (CHUNK * BB);
            mbar_wait(ps.empty[st1], (uint32_t)(ps.ecnt[st1] & 1)); ps.ecnt[st1]++;
            prefetch_chunk(hbuf_sa + (unsigned)st1 * 32768u, src, tid, ps.full[st1]);
        }
        mbar_wait(ps.full[st], (uint32_t)(ps.fcnt[st] & 1)); ps.fcnt[st]++;
        const float* hb = hbuf + (size_t)st * (CHUNK * BB);
        consume_chunk<IS_DEC>(hb, W + (size_t)i * CHUNK * 16, wout_s + i * CHUNK,
                              g, cp, rb, acc, doy, y01, y23);
        mbar_arrive(ps.empty[st]);
    }

    // ---- reduction in DEDICATED smem: store partials (no pre-sync needed) ----
    ull* red = (ull*)(smem + OFF_RED);
    float* ry = smem + OFF_RY;
    {
        ull* myp = red + (size_t)(g * 64 + (cp * 32 + rb)) * 18;
#pragma unroll
        for (int q = 0; q < 16; q += 2)
            *(ulonglong2*)(myp + q) = make_ulonglong2(acc[q], acc[q + 1]);
        if (IS_DEC && doy && cp == 0) {
            float2 ya = unpack2(y01), yb = unpack2(y23);
            *(float4*)(ry + g * BB + 4 * rb) = make_float4(ya.x, ya.y, yb.x, yb.y);
        }
    }
    __syncthreads();
    {
        int col1 = col & 1;
        int r_o = (col >> 1) * 32 + (b >> 2);
        int jj = col1 * 8 + (b & 3) * 2;
        ull aif = ((const ull*)bias_s)[col * 2];
        ull ago = ((const ull*)bias_s)[col * 2 + 1];
#pragma unroll
        for (int gg = 0; gg < 8; ++gg) {
            ulonglong2 p = *(const ulonglong2*)(red + (size_t)(gg * 64 + r_o) * 18 + jj);
            aif = add2(aif, p.x);
            ago = add2(ago, p.y);
        }
        float2 sif = unpack2(aif), sgo = unpack2(ago);
        float iv = sigf(sif.x), fv = sigf(sif.y);
        float gv = tanhfast(sgo.x), ov = sigf(sgo.y);
        cst = fv * cst + iv * gv;
        float hv = ov * tanhfast(cst);
        hdst[(size_t)(jb + col) * BB + b] = hv;
        if (IS_DEC && doy && col == 0) {
            float y = bout;
#pragma unroll
            for (int gg = 0; gg < 8; ++gg) y += ry[gg * BB + b];
            out[((size_t)b * TT + (TT - 1 - kd)) * FF + cid] = y;
        }
    }
    __syncthreads();
    if (tid == 0) {
        __threadfence();
        atomicAdd(&g_flag[gidx], 1u);
    }
}

__global__ void reset_flags_kernel() {
    if (threadIdx.x < 8) g_flag[threadIdx.x] = 16u;
}

__global__ void __launch_bounds__(NT, 1) lstm_persistent(
    const float* __restrict__ ts,
    const float* __restrict__ w_ih_enc, const float* __restrict__ w_hh_enc,
    const float* __restrict__ b_ih_enc, const float* __restrict__ b_hh_enc,
    const float* __restrict__ w_ih_dec, const float* __restrict__ w_hh_dec,
    const float* __restrict__ b_ih_dec, const float* __restrict__ b_hh_dec,
    const float* __restrict__ w_out, const float* __restrict__ b_out,
    float* __restrict__ out)
{
    extern __shared__ float smem[];
    float* Wenc   = smem + OFF_WENC;
    float* Wdec   = smem + OFF_WDEC;
    float* wout_s = smem + OFF_WOUT;
    float* bias_e = smem + OFF_BE;
    float* bias_d = smem + OFF_BD;

    const int tid = threadIdx.x;
    const int cid = blockIdx.x;
    const int g   = tid >> 6;
    const int r   = tid & 63;
    const int cp  = r >> 5;
    const int rb  = r & 31;
    const int col = tid >> 7;
    const int b   = tid & 127;
    const int jb  = cid * 4;
    const int gidx = cid >> 4;

    // mbarriers
    PipeState ps;
    {
        uint32_t mb = (uint32_t)__cvta_generic_to_shared(smem + OFF_MBAR);
        ps.full[0] = mb;      ps.full[1] = mb + 8;
        ps.empty[0] = mb + 16; ps.empty[1] = mb + 24;
        ps.fcnt[0] = ps.fcnt[1] = 0;
        ps.ecnt[0] = ps.ecnt[1] = 0;
        if (tid == 0) {
            mbar_init(ps.full[0], NT); mbar_init(ps.full[1], NT);
            mbar_init(ps.empty[0], NT); mbar_init(ps.empty[1], NT);
        }
        __syncthreads();
        // prime empties: phase 0 completes -> first producer wait passes
        mbar_arrive(ps.empty[0]);
        mbar_arrive(ps.empty[1]);
    }

    // --- encoder weights: layout [k][col(4)][gate(4)] ---
    for (int idx = tid; idx < KENC * 16; idx += NT) {
        int k = idx >> 4, rem = idx & 15, cc = rem >> 2, q = rem & 3;
        int row = q * HH + jb + cc;
        Wenc[idx] = (k < HH) ? w_hh_enc[(size_t)row * HH + k]
                             : w_ih_enc[(size_t)row * FF + (k - HH)];
    }
    // --- decoder fused weights: W_eff = w_hh_dec + w_ih_dec @ w_out ---
    for (int idx = tid; idx < HH * 16; idx += NT) {
        int k = idx >> 4, rem = idx & 15, cc = rem >> 2, q = rem & 3;
        int row = q * HH + jb + cc;
        float v = w_hh_dec[(size_t)row * HH + k];
        const float* wr = w_ih_dec + (size_t)row * FF;
#pragma unroll 8
        for (int f = 0; f < FF; ++f) v += wr[f] * w_out[(size_t)f * HH + k];
        Wdec[idx] = v;
    }
    // --- biases: layout [col][gate] ---
    if (tid < 16) {
        int cc = tid >> 2, q = tid & 3;
        int row = q * HH + jb + cc;
        bias_e[tid] = b_ih_enc[row] + b_hh_enc[row];
        float v = b_ih_dec[row] + b_hh_dec[row];
        const float* wr = w_ih_dec + (size_t)row * FF;
#pragma unroll 8
        for (int f = 0; f < FF; ++f) v += wr[f] * b_out[f];
        bias_d[tid] = v;
    }
    if (cid < FF) {
        for (int k = tid; k < HH; k += NT) wout_s[k] = w_out[(size_t)cid * HH + k];
    }
    for (int i = tid; i < 512; i += NT) g_h[0][(size_t)cid * 512 + i] = 0.0f;
    for (int tt = 0; tt < TT / NB; ++tt) {
        int t = cid * (TT / NB) + tt;
        for (int idx = tid; idx < FF * BB; idx += NT) {
            int f = idx >> 7, bb = idx & (BB - 1);
            g_xT[((size_t)t * FF + f) * BB + bb] = ts[((size_t)bb * TT + t) * FF + f];
        }
    }
    grid_barrier_init();

    const unsigned int hbuf_sa =
        (unsigned int)__cvta_generic_to_shared(smem + OFF_HBUF);
    const bool doy = (cid < FF);
    const float bout = doy ? b_out[cid] : 0.0f;

    float cst = 0.0f;

    // ================= encoder =================
    for (int s = 0; s < TT; ++s) {
        do_step<false>(s, 0, gidx, g_h[s & 1], g_h[(s + 1) & 1],
                       g_xT + (size_t)s * FF * BB,
                       Wenc, bias_e, smem, hbuf_sa,
                       wout_s, nullptr, cid, 0.0f, false,
                       tid, g, cp, rb, col, b, jb, cst, ps);
    }
    // ================= decoder =================
    cst = 0.0f;
    for (int kd = 0; kd < TT; ++kd) {
        int s = TT + kd;
        do_step<true>(s, kd, gidx, g_h[s & 1], g_h[(s + 1) & 1], nullptr,
                      Wdec, bias_d, smem, hbuf_sa,
                      wout_s, out, cid, bout, doy,
                      tid, g, cp, rb, col, b, jb, cst, ps);
    }
}

extern "C" void kernel_launch(void* const* d_in, const int* in_sizes, int n_in,
                              void* d_out, int out_size) {
    (void)in_sizes; (void)n_in; (void)out_size;
    const float* ts       = (const float*)d_in[0];
    const float* w_ih_enc = (const float*)d_in[1];
    const float* w_hh_enc = (const float*)d_in[2];
    const float* b_ih_enc = (const float*)d_in[3];
    const float* b_hh_enc = (const float*)d_in[4];
    const float* w_ih_dec = (const float*)d_in[5];
    const float* w_hh_dec = (const float*)d_in[6];
    const float* b_ih_dec = (const float*)d_in[7];
    const float* b_hh_dec = (const float*)d_in[8];
    const float* w_out    = (const float*)d_in[9];
    const float* b_out    = (const float*)d_in[10];
    float* out = (float*)d_out;

    const int smem_bytes = SMEM_FLOATS * 4;
    static bool attr_set = false;
    if (!attr_set) {
        cudaFuncSetAttribute(lstm_persistent,
                             cudaFuncAttributeMaxDynamicSharedMemorySize, smem_bytes);
        attr_set = true;
    }
    reset_flags_kernel<<<1, 32>>>();
    lstm_persistent<<<NB, NT, smem_bytes>>>(
        ts, w_ih_enc, w_hh_enc, b_ih_enc, b_hh_enc,
        w_ih_dec, w_hh_dec, b_ih_dec, b_hh_dec, w_out, b_out, out);
}

// round 7
// speedup vs baseline: 1.7044x; 1.0279x over previous
#include <cuda_runtime.h>
#include <cstdint>

#define NB 128        // CTAs (one per SM)
#define NT 544        // 1 producer warp + 16 consumer warps (512 consumers)
#define NCONS 512
#define BB 128
#define TT 1024
#define FF 64
#define HH 512
#define CHUNK 64      // k per chunk (32KB)
#define KENC (HH + FF)

typedef unsigned long long ull;

// ---------------- device scratch ----------------
__device__ float g_h[2][HH * BB];
__device__ float g_xT[TT * FF * BB];
__device__ unsigned int g_flag[8];
__device__ unsigned int g_count = 0;
__device__ unsigned int g_gen = 0;

// smem layout (float offsets)
#define OFF_WENC 0               // 9216
#define OFF_WDEC 9216            // 8192
#define OFF_HBUF 17408           // 2 x 8192
#define OFF_RED  33792           // 18432
#define OFF_RY   52224           // 1024
#define OFF_WOUT 53248           // 512
#define OFF_BE   53760           // 16
#define OFF_BD   53776           // 16
#define OFF_MBAR 53792           // 4 mbarriers (32B)
#define OFF_RDY  53800           // ready counter (int)
#define SMEM_FLOATS 53808

__device__ __forceinline__ ull pack2(float x, float y) {
    ull r; asm("mov.b64 %0, {%1, %2};" : "=l"(r) : "f"(x), "f"(y)); return r;
}
__device__ __forceinline__ float2 unpack2(ull v) {
    float2 r; asm("mov.b64 {%0, %1}, %2;" : "=f"(r.x), "=f"(r.y) : "l"(v)); return r;
}
__device__ __forceinline__ void fma2(ull& d, ull a, ull b) {
    asm("fma.rn.f32x2 %0, %1, %2, %0;" : "+l"(d) : "l"(a), "l"(b));
}
__device__ __forceinline__ ull add2(ull a, ull b) {
    ull r; asm("add.rn.f32x2 %0, %1, %2;" : "=l"(r) : "l"(a), "l"(b)); return r;
}
__device__ __forceinline__ float sigf(float x) {
    return __fdividef(1.0f, 1.0f + __expf(-x));
}
__device__ __forceinline__ float tanhfast(float x) {
    return 1.0f - __fdividef(2.0f, __expf(2.0f * x) + 1.0f);
}

// ---------------- mbarrier primitives ----------------
__device__ __forceinline__ void mbar_init(uint32_t a, uint32_t cnt) {
    asm volatile("mbarrier.init.shared.b64 [%0], %1;" :: "r"(a), "r"(cnt) : "memory");
}
__device__ __forceinline__ void mbar_arrive(uint32_t a) {
    asm volatile("mbarrier.arrive.shared.b64 _, [%0];" :: "r"(a) : "memory");
}
__device__ __forceinline__ void mbar_expect_tx(uint32_t a, uint32_t bytes) {
    asm volatile("mbarrier.arrive.expect_tx.shared.b64 _, [%0], %1;"
                 :: "r"(a), "r"(bytes) : "memory");
}
__device__ __forceinline__ void mbar_wait(uint32_t a, uint32_t parity) {
    asm volatile(
        "{\n\t.reg .pred P;\n"
        "WL_%=:\n\t"
        "mbarrier.try_wait.parity.shared.b64 P, [%0], %1, 0x989680;\n\t"
        "@P bra WD_%=;\n\t"
        "bra WL_%=;\n"
        "WD_%=:\n\t}"
        :: "r"(a), "r"(parity) : "memory");
}
__device__ __forceinline__ void bulk_copy(uint32_t dst, const float* src, uint32_t mbar) {
    asm volatile(
        "cp.async.bulk.shared::cta.global.mbarrier::complete_tx::bytes [%0], [%1], %2, [%3];"
        :: "r"(dst), "l"(src), "r"(32768u), "r"(mbar) : "memory");
}

__device__ __forceinline__ void grid_barrier_init() {
    __syncthreads();
    if (threadIdx.x == 0) {
        unsigned int cur0;
        asm volatile("ld.acquire.gpu.b32 %0, [%1];" : "=r"(cur0) : "l"(&g_gen) : "memory");
        unsigned int target = cur0 + 1u;
        __threadfence();
        unsigned int t = atomicAdd(&g_count, 1u);
        if (t == NB - 1u) {
            g_count = 0u;
            asm volatile("st.release.gpu.b32 [%0], %1;" :: "l"(&g_gen), "r"(target) : "memory");
        } else {
            unsigned int cur;
            do {
                __nanosleep(20);
                asm volatile("ld.acquire.gpu.b32 %0, [%1];" : "=r"(cur) : "l"(&g_gen) : "memory");
            } while ((int)(cur - target) < 0);
        }
    }
    __syncthreads();
}

__device__ __forceinline__ void wait_flag(int ch, unsigned int tgt) {
    unsigned int v;
    asm volatile("ld.acquire.gpu.b32 %0, [%1];" : "=r"(v) : "l"(&g_flag[ch]) : "memory");
    while ((int)(v - tgt) < 0) {
        __nanosleep(32);
        asm volatile("ld.acquire.gpu.b32 %0, [%1];" : "=r"(v) : "l"(&g_flag[ch]) : "memory");
    }
}

// consumer spin on smem ready counter (producer-published, monotonic)
__device__ __forceinline__ void wait_ready(uint32_t raddr, int needed) {
    int v;
    asm volatile("ld.acquire.cta.shared.b32 %0, [%1];" : "=r"(v) : "r"(raddr) : "memory");
    while (v < needed) {
        __nanosleep(32);
        asm volatile("ld.acquire.cta.shared.b32 %0, [%1];" : "=r"(v) : "r"(raddr) : "memory");
    }
}

// consume one staged chunk: 8 k values (stride 8), 2 cols x 4 gates x 4 batches
template <bool IS_DEC>
__device__ __forceinline__ void consume_chunk(
    const float* hb, const float* Wk, const float* wo,
    int g, int cp, int rb, ull* acc, bool doy, ull& y01, ull& y23)
{
    const float4* hp = (const float4*)hb + (g * 32 + rb);
    const ulonglong2* wp = (const ulonglong2*)Wk + (g * 4 + cp * 2);
#pragma unroll
    for (int t = 0; t < 8; ++t) {
        float4 h4 = hp[t * 256];
        ulonglong2 wa = wp[t * 32];          // colA: (wi,wf),(wg,wo)
        ulonglong2 wb = wp[t * 32 + 1];      // colB
        ull h0 = pack2(h4.x, h4.x), h1 = pack2(h4.y, h4.y);
        ull h2 = pack2(h4.z, h4.z), h3 = pack2(h4.w, h4.w);
        fma2(acc[0],  wa.x, h0); fma2(acc[1],  wa.y, h0);
        fma2(acc[2],  wa.x, h1); fma2(acc[3],  wa.y, h1);
        fma2(acc[4],  wa.x, h2); fma2(acc[5],  wa.y, h2);
        fma2(acc[6],  wa.x, h3); fma2(acc[7],  wa.y, h3);
        fma2(acc[8],  wb.x, h0); fma2(acc[9],  wb.y, h0);
        fma2(acc[10], wb.x, h1); fma2(acc[11], wb.y, h1);
        fma2(acc[12], wb.x, h2); fma2(acc[13], wb.y, h2);
        fma2(acc[14], wb.x, h3); fma2(acc[15], wb.y, h3);
        if (IS_DEC && doy) {
            float w = wo[g + 8 * t];
            ull ws = pack2(w, w);
            fma2(y01, ws, ((const ull*)&h4)[0]);
            fma2(y23, ws, ((const ull*)&h4)[1]);
        }
    }
}

__global__ void reset_flags_kernel() {
    if (threadIdx.x < 8) g_flag[threadIdx.x] = 16u;
}

__global__ void __launch_bounds__(NT, 1) lstm_persistent(
    const float* __restrict__ ts,
    const float* __restrict__ w_ih_enc, const float* __restrict__ w_hh_enc,
    const float* __restrict__ b_ih_enc, const float* __restrict__ b_hh_enc,
    const float* __restrict__ w_ih_dec, const float* __restrict__ w_hh_dec,
    const float* __restrict__ b_ih_dec, const float* __restrict__ b_hh_dec,
    const float* __restrict__ w_out, const float* __restrict__ b_out,
    float* __restrict__ out)
{
    extern __shared__ float smem[];
    float* Wenc   = smem + OFF_WENC;
    float* Wdec   = smem + OFF_WDEC;
    float* hbuf   = smem + OFF_HBUF;
    float* wout_s = smem + OFF_WOUT;
    float* bias_e = smem + OFF_BE;
    float* bias_d = smem + OFF_BD;

    const int tid = threadIdx.x;
    const int cid = blockIdx.x;
    const int jb  = cid * 4;
    const int gidx = cid >> 4;

    uint32_t mb = (uint32_t)__cvta_generic_to_shared(smem + OFF_MBAR);
    const uint32_t full0 = mb, full1 = mb + 8, empty0 = mb + 16, empty1 = mb + 24;
    const uint32_t raddr = (uint32_t)__cvta_generic_to_shared(smem + OFF_RDY);
    const uint32_t hbuf_sa = (uint32_t)__cvta_generic_to_shared(hbuf);

    if (tid == 0) {
        mbar_init(full0, 1); mbar_init(full1, 1);
        mbar_init(empty0, NCONS); mbar_init(empty1, NCONS);
        *(int*)(smem + OFF_RDY) = 0;
        asm volatile("fence.proxy.async.shared::cta;" ::: "memory");
    }

    // --- weights / biases / state init (all 544 threads) ---
    for (int idx = tid; idx < KENC * 16; idx += NT) {
        int k = idx >> 4, rem = idx & 15, cc = rem >> 2, q = rem & 3;
        int row = q * HH + jb + cc;
        Wenc[idx] = (k < HH) ? w_hh_enc[(size_t)row * HH + k]
                             : w_ih_enc[(size_t)row * FF + (k - HH)];
    }
    for (int idx = tid; idx < HH * 16; idx += NT) {
        int k = idx >> 4, rem = idx & 15, cc = rem >> 2, q = rem & 3;
        int row = q * HH + jb + cc;
        float v = w_hh_dec[(size_t)row * HH + k];
        const float* wr = w_ih_dec + (size_t)row * FF;
#pragma unroll 8
        for (int f = 0; f < FF; ++f) v += wr[f] * w_out[(size_t)f * HH + k];
        Wdec[idx] = v;
    }
    if (tid < 16) {
        int cc = tid >> 2, q = tid & 3;
        int row = q * HH + jb + cc;
        bias_e[tid] = b_ih_enc[row] + b_hh_enc[row];
        float v = b_ih_dec[row] + b_hh_dec[row];
        const float* wr = w_ih_dec + (size_t)row * FF;
#pragma unroll 8
        for (int f = 0; f < FF; ++f) v += wr[f] * b_out[f];
        bias_d[tid] = v;
    }
    if (cid < FF) {
        for (int k = tid; k < HH; k += NT) wout_s[k] = w_out[(size_t)cid * HH + k];
    }
    for (int i = tid; i < 512; i += NT) g_h[0][(size_t)cid * 512 + i] = 0.0f;
    for (int tt = 0; tt < TT / NB; ++tt) {
        int t = cid * (TT / NB) + tt;
        for (int idx = tid; idx < FF * BB; idx += NT) {
            int f = idx >> 7, bb = idx & (BB - 1);
            g_xT[((size_t)t * FF + f) * BB + bb] = ts[((size_t)bb * TT + t) * FF + f];
        }
    }
    __syncthreads();
    // prime both empty phases (consumers arrive once per stage)
    if (tid >= 32) { mbar_arrive(empty0); mbar_arrive(empty1); }
    grid_barrier_init();

    if (tid < 32) {
        // ================= PRODUCER (lane 0 of warp 0) =================
        if (tid == 0) {
            int ctr = 0, ecnt0 = 0, ecnt1 = 0, fcnt0 = 0, fcnt1 = 0;
            for (int s = 0; s < 2 * TT; ++s) {
                const bool enc = (s < TT);
                const int nc = enc ? 9 : 8;
                const float* hsrc = g_h[s & 1];
                const unsigned int tgt = 16u * (unsigned)(s + 1);
                for (int i = 0; i < nc; ++i) {
                    int st = ctr & 1;
                    if (st == 0) { mbar_wait(empty0, ecnt0 & 1); ecnt0++; }
                    else         { mbar_wait(empty1, ecnt1 & 1); ecnt1++; }
                    const float* src;
                    if (enc && i == 8) {
                        src = g_xT + (size_t)s * (FF * BB);
                    } else {
                        int ch = (gidx + i) & 7;
                        wait_flag(ch, tgt);
                        src = hsrc + (size_t)ch * (CHUNK * BB);
                    }
                    uint32_t fb = st ? full1 : full0;
                    mbar_expect_tx(fb, 32768u);
                    bulk_copy(hbuf_sa + (unsigned)st * 32768u, src, fb);
                    if (st == 0) { mbar_wait(full0, fcnt0 & 1); fcnt0++; }
                    else         { mbar_wait(full1, fcnt1 & 1); fcnt1++; }
                    ctr++;
                    asm volatile("st.release.cta.shared.b32 [%0], %1;"
                                 :: "r"(raddr), "r"(ctr) : "memory");
                }
            }
        }
        return;   // producer warp (all lanes) exits the consumer path
    }

    // ================= CONSUMERS (512 threads) =================
    const int ctid = tid - 32;
    const int g   = ctid >> 6;
    const int r   = ctid & 63;
    const int cp  = r >> 5;
    const int rb  = r & 31;
    const int col = ctid >> 7;
    const int b   = ctid & 127;
    const bool doy = (cid < FF);
    const float bout = doy ? b_out[cid] : 0.0f;

    ull* red = (ull*)(smem + OFF_RED);
    float* ry = smem + OFF_RY;

    float cst = 0.0f;
    int ctr = 0;

    for (int s = 0; s < 2 * TT; ++s) {
        const bool enc = (s < TT);
        const int nc = enc ? 9 : 8;
        const int kd = s - TT;
        if (s == TT) cst = 0.0f;                // decoder resets c
        float* hdst = g_h[(s + 1) & 1];

        ull acc[16];
#pragma unroll
        for (int q = 0; q < 16; ++q) acc[q] = 0ull;
        ull y01 = 0ull, y23 = 0ull;

        for (int i = 0; i < nc; ++i) {
            int st = ctr & 1;
            wait_ready(raddr, ctr + 1);
            const float* hb = hbuf + (size_t)st * (CHUNK * BB);
            int ch = (enc && i == 8) ? 8 : ((gidx + i) & 7);
            if (enc && !doy)
                consume_chunk<false>(hb, Wenc + (size_t)ch * (CHUNK * 16),
                                     wout_s, g, cp, rb, acc, false, y01, y23);
            else if (enc)
                consume_chunk<false>(hb, Wenc + (size_t)ch * (CHUNK * 16),
                                     wout_s, g, cp, rb, acc, false, y01, y23);
            else
                consume_chunk<true>(hb, Wdec + (size_t)ch * (CHUNK * 16),
                                    wout_s + ch * CHUNK, g, cp, rb, acc, doy, y01, y23);
            mbar_arrive(st ? empty1 : empty0);
            ctr++;
        }

        // ---- epilogue: reduce across 8 kgroups ----
        {
            ull* myp = red + (size_t)(g * 64 + (cp * 32 + rb)) * 18;
#pragma unroll
            for (int q = 0; q < 16; q += 2)
                *(ulonglong2*)(myp + q) = make_ulonglong2(acc[q], acc[q + 1]);
            if (!enc && doy && cp == 0) {
                float2 ya = unpack2(y01), yb = unpack2(y23);
                *(float4*)(ry + g * BB + 4 * rb) = make_float4(ya.x, ya.y, yb.x, yb.y);
            }
        }
        asm volatile("bar.sync 1, %0;" :: "n"(NCONS) : "memory");
        {
            const float* bias_s = enc ? bias_e : bias_d;
            int col1 = col & 1;
            int r_o = (col >> 1) * 32 + (b >> 2);
            int jj = col1 * 8 + (b & 3) * 2;
            ull aif = ((const ull*)bias_s)[col * 2];
            ull ago = ((const ull*)bias_s)[col * 2 + 1];
#pragma unroll
            for (int gg = 0; gg < 8; ++gg) {
                ulonglong2 p = *(const ulonglong2*)(red + (size_t)(gg * 64 + r_o) * 18 + jj);
                aif = add2(aif, p.x);
                ago = add2(ago, p.y);
            }
            float2 sif = unpack2(aif), sgo = unpack2(ago);
            float iv = sigf(sif.x), fv = sigf(sif.y);
            float gv = tanhfast(sgo.x), ov = sigf(sgo.y);
            cst = fv * cst + iv * gv;
            float hv = ov * tanhfast(cst);
            hdst[(size_t)(jb + col) * BB + b] = hv;
            if (!enc && doy && col == 0) {
                float y = bout;
#pragma unroll
                for (int gg = 0; gg < 8; ++gg) y += ry[gg * BB + b];
                out[((size_t)b * TT + (TT - 1 - kd)) * FF + cid] = y;
            }
        }
        asm volatile("bar.sync 1, %0;" :: "n"(NCONS) : "memory");
        if (ctid == 0) {
            __threadfence();
            atomicAdd(&g_flag[gidx], 1u);
        }
    }
}

extern "C" void kernel_launch(void* const* d_in, const int* in_sizes, int n_in,
                              void* d_out, int out_size) {
    (void)in_sizes; (void)n_in; (void)out_size;
    const float* ts       = (const float*)d_in[0];
    const float* w_ih_enc = (const float*)d_in[1];
    const float* w_hh_enc = (const float*)d_in[2];
    const float* b_ih_enc = (const float*)d_in[3];
    const float* b_hh_enc = (const float*)d_in[4];
    const float* w_ih_dec = (const float*)d_in[5];
    const float* w_hh_dec = (const float*)d_in[6];
    const float* b_ih_dec = (const float*)d_in[7];
    const float* b_hh_dec = (const float*)d_in[8];
    const float* w_out    = (const float*)d_in[9];
    const float* b_out    = (const float*)d_in[10];
    float* out = (float*)d_out;

    const int smem_bytes = SMEM_FLOATS * 4;
    static bool attr_set = false;
    if (!attr_set) {
        cudaFuncSetAttribute(lstm_persistent,
                             cudaFuncAttributeMaxDynamicSharedMemorySize, smem_bytes);
        attr_set = true;
    }
    reset_flags_kernel<<<1, 32>>>();
    lstm_persistent<<<NB, NT, smem_bytes>>>(
        ts, w_ih_enc, w_hh_enc, b_ih_enc, b_hh_enc,
        w_ih_dec, w_hh_dec, b_ih_dec, b_hh_dec, w_out, b_out, out);
}

// round 10
// speedup vs baseline: 2.5803x; 1.5139x over previous
#include <cuda_runtime.h>
#include <cuda_bf16.h>
#include <cstdint>

#define NB 128
#define NT 256          // 8 compute warps
#define BB 128
#define TT 1024
#define FF 64
#define HH 512

typedef unsigned long long ull;

// ---------------- device scratch ----------------
__device__ __align__(1024) unsigned char g_hhi[2][8 * 16384];
__device__ __align__(1024) unsigned char g_hlo[2][8 * 16384];
__device__ __align__(1024) unsigned char g_xhi[(size_t)TT * 16384];
__device__ __align__(1024) unsigned char g_xlo[(size_t)TT * 16384];
__device__ float g_hist[(size_t)TT * HH * BB];   // decoder-input h [kd][j][b]
__device__ float g_woutT[HH * FF];
__device__ unsigned int g_flag[8];
__device__ unsigned int g_count = 0, g_gen = 0;

// ---------------- smem byte offsets ----------------
#define OFF_WBE  0          // enc B frags: 9 ch * 4096
#define OFF_WBD  36864      // dec B frags: 8 ch * 4096
#define OFF_A    69632      // 3 stages * 32768 (hi 16K + lo 16K)
#define OFF_BE   167936     // 16 floats
#define OFF_BD   168000     // 16 floats
#define SMEM_BYTES 168064

static __device__ __forceinline__ uint32_t sw128(uint32_t o) {
    return o ^ ((o >> 3) & 0x70);
}
__device__ __forceinline__ float sigf(float x) {
    return __fdividef(1.0f, 1.0f + __expf(-x));
}
__device__ __forceinline__ float tanhfast(float x) {
    return 1.0f - __fdividef(2.0f, __expf(2.0f * x) + 1.0f);
}

__device__ __forceinline__ void grid_barrier_init() {
    __syncthreads();
    if (threadIdx.x == 0) {
        unsigned int cur0;
        asm volatile("ld.acquire.gpu.b32 %0, [%1];" : "=r"(cur0) : "l"(&g_gen) : "memory");
        unsigned int target = cur0 + 1u;
        __threadfence();
        unsigned int t = atomicAdd(&g_count, 1u);
        if (t == NB - 1u) {
            g_count = 0u;
            asm volatile("st.release.gpu.b32 [%0], %1;" :: "l"(&g_gen), "r"(target) : "memory");
        } else {
            unsigned int cur;
            do {
                __nanosleep(20);
                asm volatile("ld.acquire.gpu.b32 %0, [%1];" : "=r"(cur) : "l"(&g_gen) : "memory");
            } while ((int)(cur - target) < 0);
        }
    }
    __syncthreads();
}
__device__ __forceinline__ void wait_flag(int ch, unsigned int tgt) {
    unsigned int v;
    asm volatile("ld.acquire.gpu.b32 %0, [%1];" : "=r"(v) : "l"(&g_flag[ch]) : "memory");
    while ((int)(v - tgt) < 0) {
        __nanosleep(32);
        asm volatile("ld.acquire.gpu.b32 %0, [%1];" : "=r"(v) : "l"(&g_flag[ch]) : "memory");
    }
}

// stage one 32KB (hi+lo) chunk: 8 cp.async.cg per thread, one commit group
__device__ __forceinline__ void prefetch_chunk(uint32_t dst, const unsigned char* hi,
                                               const unsigned char* lo, int tid) {
#pragma unroll
    for (int i = 0; i < 4; i++) {
        uint32_t off = (uint32_t)(tid + NT * i) * 16u;
        asm volatile("cp.async.cg.shared.global [%0], [%1], 16;"
                     :: "r"(dst + off), "l"(hi + off) : "memory");
        asm volatile("cp.async.cg.shared.global [%0], [%1], 16;"
                     :: "r"(dst + 16384u + off), "l"(lo + off) : "memory");
    }
    asm volatile("cp.async.commit_group;" ::: "memory");
}

__device__ __forceinline__ void ldmx4(uint32_t addr, uint32_t* a) {
    asm volatile("ldmatrix.sync.aligned.m8n8.x4.shared.b16 {%0,%1,%2,%3}, [%4];"
                 : "=r"(a[0]), "=r"(a[1]), "=r"(a[2]), "=r"(a[3]) : "r"(addr));
}
__device__ __forceinline__ void mma16816(float* d, const uint32_t* a, uint32_t b0, uint32_t b1) {
    asm volatile(
        "mma.sync.aligned.m16n8k16.row.col.f32.bf16.bf16.f32 "
        "{%0,%1,%2,%3}, {%4,%5,%6,%7}, {%8,%9}, {%0,%1,%2,%3};"
        : "+f"(d[0]), "+f"(d[1]), "+f"(d[2]), "+f"(d[3])
        : "r"(a[0]), "r"(a[1]), "r"(a[2]), "r"(a[3]), "r"(b0), "r"(b1));
}
__device__ __forceinline__ uint32_t pack_bf16x2(float lo, float hi) {
    uint32_t r;
    asm("cvt.rn.bf16x2.f32 %0, %1, %2;" : "=r"(r) : "f"(hi), "f"(lo));
    return r;
}

// consume one staged chunk: 8 ldmatrix + 16 LDS.64 + 24 HMMA
__device__ __forceinline__ void consume_chunk(uint32_t sa, uint32_t wb,
                                              uint32_t abase, int lane,
                                              float* D0, float* D1) {
#pragma unroll
    for (int ks = 0; ks < 4; ++ks) {
        uint32_t ao = sw128(abase + (uint32_t)ks * 32u);
        uint32_t ahi[4], alo[4];
        ldmx4(sa + ao, ahi);
        ldmx4(sa + 16384u + ao, alo);
#pragma unroll
        for (int nt = 0; nt < 2; ++nt) {
            uint32_t fb = wb + (uint32_t)(ks * 2 + nt) * 512u + (uint32_t)lane * 8u;
            uint32_t bh0, bh1, bl0, bl1;
            asm("ld.shared.v2.b32 {%0,%1}, [%2];" : "=r"(bh0), "=r"(bh1) : "r"(fb));
            asm("ld.shared.v2.b32 {%0,%1}, [%2];" : "=r"(bl0), "=r"(bl1) : "r"(fb + 256u));
            float* D = nt ? D1 : D0;
            mma16816(D, ahi, bh0, bh1);
            mma16816(D, alo, bh0, bh1);
            mma16816(D, ahi, bl0, bl1);
        }
    }
}

__global__ void reset_flags_kernel() {
    if (threadIdx.x < 8) g_flag[threadIdx.x] = 16u;   // h_0 ready baseline
}

__global__ void __launch_bounds__(NT, 1) lstm_persistent(
    const float* __restrict__ ts,
    const float* __restrict__ w_ih_enc, const float* __restrict__ w_hh_enc,
    const float* __restrict__ b_ih_enc, const float* __restrict__ b_hh_enc,
    const float* __restrict__ w_ih_dec, const float* __restrict__ w_hh_dec,
    const float* __restrict__ b_ih_dec, const float* __restrict__ b_hh_dec,
    const float* __restrict__ w_out, const float* __restrict__ b_out,
    float* __restrict__ out)
{
    extern __shared__ unsigned char smem[];
    const int tid = threadIdx.x;
    const int cid = blockIdx.x;
    const int jb = cid * 4;
    const int gidx = cid >> 4;
    const uint32_t sb = (uint32_t)__cvta_generic_to_shared(smem);

    // ======== INIT: encoder B fragments (chunks 0..7 = h, 8 = x) ========
    for (int e = tid; e < 9 * 4 * 2 * 32; e += NT) {
        int lane = e & 31, rem = e >> 5;
        int nt = rem & 1, ks = (rem >> 1) & 3, ch = rem >> 3;
        int gid = lane >> 2, tig = lane & 3;
        int n = nt * 8 + gid, jl = n >> 2, q = n & 3;
        int row = q * HH + jb + jl;
        float v[4];
#pragma unroll
        for (int d = 0; d < 4; ++d) {
            int kin = ks * 16 + 2 * tig + ((d & 2) ? 8 : 0) + (d & 1);
            v[d] = (ch < 8) ? w_hh_enc[(size_t)row * HH + ch * 64 + kin]
                            : w_ih_enc[(size_t)row * FF + kin];
        }
        float hi[4], lo[4];
#pragma unroll
        for (int d = 0; d < 4; ++d) {
            hi[d] = __bfloat162float(__float2bfloat16(v[d]));
            lo[d] = v[d] - hi[d];
        }
        uint32_t base = (uint32_t)(ch * 8 + ks * 2 + nt) * 512u + (uint32_t)lane * 8u;
        uint32_t* ph = (uint32_t*)(smem + OFF_WBE + base);
        uint32_t* pl = (uint32_t*)(smem + OFF_WBE + base + 256);
        ph[0] = pack_bf16x2(hi[0], hi[1]); ph[1] = pack_bf16x2(hi[2], hi[3]);
        pl[0] = pack_bf16x2(lo[0], lo[1]); pl[1] = pack_bf16x2(lo[2], lo[3]);
    }
    // ======== INIT: decoder fused B fragments (W_eff = w_hh + w_ih @ w_out) ========
    for (int e = tid; e < 8 * 4 * 2 * 32; e += NT) {
        int lane = e & 31, rem = e >> 5;
        int nt = rem & 1, ks = (rem >> 1) & 3, ch = rem >> 3;
        int gid = lane >> 2, tig = lane & 3;
        int n = nt * 8 + gid, jl = n >> 2, q = n & 3;
        int row = q * HH + jb + jl;
        const float* wr = w_ih_dec + (size_t)row * FF;
        float v[4];
#pragma unroll
        for (int d = 0; d < 4; ++d) {
            int k = ch * 64 + ks * 16 + 2 * tig + ((d & 2) ? 8 : 0) + (d & 1);
            float acc = w_hh_dec[(size_t)row * HH + k];
#pragma unroll 8
            for (int f = 0; f < FF; ++f) acc += wr[f] * w_out[(size_t)f * HH + k];
            v[d] = acc;
        }
        float hi[4], lo[4];
#pragma unroll
        for (int d = 0; d < 4; ++d) {
            hi[d] = __bfloat162float(__float2bfloat16(v[d]));
            lo[d] = v[d] - hi[d];
        }
        uint32_t base = (uint32_t)(ch * 8 + ks * 2 + nt) * 512u + (uint32_t)lane * 8u;
        uint32_t* ph = (uint32_t*)(smem + OFF_WBD + base);
        uint32_t* pl = (uint32_t*)(smem + OFF_WBD + base + 256);
        ph[0] = pack_bf16x2(hi[0], hi[1]); ph[1] = pack_bf16x2(hi[2], hi[3]);
        pl[0] = pack_bf16x2(lo[0], lo[1]); pl[1] = pack_bf16x2(lo[2], lo[3]);
    }
    // biases [jl][q]
    if (tid < 16) {
        int jl = tid >> 2, q = tid & 3;
        int row = q * HH + jb + jl;
        ((float*)(smem + OFF_BE))[jl * 4 + q] = b_ih_enc[row] + b_hh_enc[row];
        float v = b_ih_dec[row] + b_hh_dec[row];
        const float* wr = w_ih_dec + (size_t)row * FF;
#pragma unroll 8
        for (int f = 0; f < FF; ++f) v += wr[f] * b_out[f];
        ((float*)(smem + OFF_BD))[jl * 4 + q] = v;
    }
    // x tiles: [t][b*128B] bf16 hi/lo, swizzled; 8 t per CTA
    for (int tt = 0; tt < TT / NB; ++tt) {
        int t = cid * (TT / NB) + tt;
        for (int idx = tid; idx < BB * 16; idx += NT) {
            int b = idx >> 4, f4 = (idx & 15) * 4;
            float v0 = ts[((size_t)b * TT + t) * FF + f4];
            float v1 = ts[((size_t)b * TT + t) * FF + f4 + 1];
            float v2 = ts[((size_t)b * TT + t) * FF + f4 + 2];
            float v3 = ts[((size_t)b * TT + t) * FF + f4 + 3];
            uint32_t h01 = pack_bf16x2(v0, v1), h23 = pack_bf16x2(v2, v3);
            float r0 = v0 - __bfloat162float(__float2bfloat16(v0));
            float r1 = v1 - __bfloat162float(__float2bfloat16(v1));
            float r2 = v2 - __bfloat162float(__float2bfloat16(v2));
            float r3 = v3 - __bfloat162float(__float2bfloat16(v3));
            uint32_t l01 = pack_bf16x2(r0, r1), l23 = pack_bf16x2(r2, r3);
            uint32_t o = sw128((uint32_t)(b * 128 + f4 * 2));
            *(uint2*)(g_xhi + (size_t)t * 16384 + o) = make_uint2(h01, h23);
            *(uint2*)(g_xlo + (size_t)t * 16384 + o) = make_uint2(l01, l23);
        }
    }
    // zero own h_0 slice (4 cols x 128 b), both splits
    if (tid < 128) {
        uint32_t o = sw128((uint32_t)(tid * 128 + (cid & 15) * 8));
        *(uint2*)(g_hhi[0] + (size_t)gidx * 16384 + o) = make_uint2(0, 0);
        *(uint2*)(g_hlo[0] + (size_t)gidx * 16384 + o) = make_uint2(0, 0);
    }
    if (cid == 0) {
        for (int idx = tid; idx < HH * FF; idx += NT) {
            int j = idx >> 6, f = idx & 63;
            g_woutT[j * FF + f] = w_out[(size_t)f * HH + j];
        }
    }
    grid_barrier_init();

    // ======== persistent recurrence ========
    const int w = tid >> 5, lane = tid & 31;
    const int gid = lane >> 2, tig = lane & 3;
    const uint32_t abase = (uint32_t)(((w << 4) + (lane & 15)) * 128 + ((lane >> 4) & 1) * 16);

    float c0s = 0.0f, c8s = 0.0f;

    for (int s = 0; s < 2 * TT; ++s) {
        const bool enc = (s < TT);
        const int nc = enc ? 9 : 8;
        if (s == TT) { c0s = 0.0f; c8s = 0.0f; }
        const unsigned int tgt = 16u * (unsigned)(s + 1);

        if (tid < 8) wait_flag(tid, tgt);    // parallel upfront wait for all h chunks
        __syncthreads();

        const unsigned char* hhi = g_hhi[s & 1];
        const unsigned char* hlo = g_hlo[s & 1];
        // src(i): enc: i==0 -> x(t=s), else h chunk i-1 ; dec: h chunk i
#define SRC_HI(i) (enc ? ((i) == 0 ? g_xhi + (size_t)s * 16384 : hhi + (size_t)((i) - 1) * 16384) \
                       : hhi + (size_t)(i) * 16384)
#define SRC_LO(i) (enc ? ((i) == 0 ? g_xlo + (size_t)s * 16384 : hlo + (size_t)((i) - 1) * 16384) \
                       : hlo + (size_t)(i) * 16384)

        prefetch_chunk(sb + OFF_A, SRC_HI(0), SRC_LO(0), tid);
        prefetch_chunk(sb + OFF_A + 32768u, SRC_HI(1), SRC_LO(1), tid);

        float D0[4] = {0, 0, 0, 0}, D1[4] = {0, 0, 0, 0};

        for (int i = 0; i < nc; ++i) {
            if (i + 1 < nc) {
                asm volatile("cp.async.wait_group 1;" ::: "memory");
            } else {
                asm volatile("cp.async.wait_group 0;" ::: "memory");
            }
            __syncthreads();   // chunk i landed everywhere; stage (i+2)%3 free
            if (i + 2 < nc) {
                prefetch_chunk(sb + OFF_A + (uint32_t)((i + 2) % 3) * 32768u,
                               SRC_HI(i + 2), SRC_LO(i + 2), tid);
            }
            int ch = enc ? (i == 0 ? 8 : i - 1) : i;
            uint32_t wb = sb + (enc ? OFF_WBE : OFF_WBD) + (uint32_t)ch * 4096u;
            consume_chunk(sb + OFF_A + (uint32_t)(i % 3) * 32768u, wb, abase, lane, D0, D1);
        }
#undef SRC_HI
#undef SRC_LO

        // ---- epilogue: gate pairing via shfl, cell update ----
        bool ev = ((tig & 1) == 0);
        float s0 = ev ? D1[0] : D0[0];
        float s1 = ev ? D1[1] : D0[1];
        float s2 = ev ? D1[2] : D0[2];
        float s3 = ev ? D1[3] : D0[3];
        float r0 = __shfl_xor_sync(0xffffffffu, s0, 1);
        float r1 = __shfl_xor_sync(0xffffffffu, s1, 1);
        float r2 = __shfl_xor_sync(0xffffffffu, s2, 1);
        float r3 = __shfl_xor_sync(0xffffffffu, s3, 1);
        float gi0, gf0, gi8, gf8, gg0, go0, gg8, go8;
        int jl;
        if (ev) {
            gi0 = D0[0]; gf0 = D0[1]; gi8 = D0[2]; gf8 = D0[3];
            gg0 = r0; go0 = r1; gg8 = r2; go8 = r3;
            jl = tig >> 1;
        } else {
            gi0 = r0; gf0 = r1; gi8 = r2; gf8 = r3;
            gg0 = D1[0]; go0 = D1[1]; gg8 = D1[2]; go8 = D1[3];
            jl = (tig >> 1) + 2;
        }
        float4 bi = ((const float4*)(smem + (enc ? OFF_BE : OFF_BD)))[jl];
        float iv0 = sigf(gi0 + bi.x), fv0 = sigf(gf0 + bi.y);
        float gv0 = tanhfast(gg0 + bi.z), ov0 = sigf(go0 + bi.w);
        float iv8 = sigf(gi8 + bi.x), fv8 = sigf(gf8 + bi.y);
        float gv8 = tanhfast(gg8 + bi.z), ov8 = sigf(go8 + bi.w);
        c0s = fv0 * c0s + iv0 * gv0;
        c8s = fv8 * c8s + iv8 * gv8;
        float h0 = ov0 * tanhfast(c0s);
        float h8 = ov8 * tanhfast(c8s);

        int b0r = (w << 4) + gid;
        uint32_t colb = (uint32_t)((((cid & 15) << 2) + jl) << 1);
        uint32_t o0 = sw128((uint32_t)(b0r * 128) + colb);
        uint32_t o8 = sw128((uint32_t)((b0r + 8) * 128) + colb);
        int nb2 = (s + 1) & 1;
        size_t tb = (size_t)gidx * 16384;
        __nv_bfloat16 h0h = __float2bfloat16(h0);
        __nv_bfloat16 h8h = __float2bfloat16(h8);
        *(__nv_bfloat16*)(g_hhi[nb2] + tb + o0) = h0h;
        *(__nv_bfloat16*)(g_hhi[nb2] + tb + o8) = h8h;
        *(__nv_bfloat16*)(g_hlo[nb2] + tb + o0) = __float2bfloat16(h0 - __bfloat162float(h0h));
        *(__nv_bfloat16*)(g_hlo[nb2] + tb + o8) = __float2bfloat16(h8 - __bfloat162float(h8h));
        if (s >= TT - 1 && s < 2 * TT - 1) {
            int kd = s - (TT - 1);
            float* hb = g_hist + ((size_t)kd * HH + (jb + jl)) * BB;
            hb[b0r] = h0;
            hb[b0r + 8] = h8;
        }
        __syncthreads();
        if (tid == 0) {
            __threadfence();
            atomicAdd(&g_flag[gidx], 1u);
        }
    }
}

// ============ final y pass: out[b][T-1-kd][:] = hist[kd]·w_outT + b_out ============
__global__ void __launch_bounds__(128) y_final(const float* __restrict__ b_out,
                                               float* __restrict__ out) {
    const int kd = blockIdx.x;
    const int b = threadIdx.x;
    ull acc[32];
#pragma unroll
    for (int q = 0; q < 32; ++q) {
        float2 bo = *(const float2*)(b_out + 2 * q);
        asm("mov.b64 %0, {%1, %2};" : "=l"(acc[q]) : "f"(bo.x), "f"(bo.y));
    }
    const float* hp = g_hist + (size_t)kd * HH * BB + b;
#pragma unroll 4
    for (int j = 0; j < HH; ++j) {
        float hv = hp[(size_t)j * BB];
        ull h2;
        asm("mov.b64 %0, {%1, %2};" : "=l"(h2) : "f"(hv), "f"(hv));
        const ulonglong2* wp = (const ulonglong2*)(g_woutT + j * FF);
#pragma unroll
        for (int q = 0; q < 16; ++q) {
            ulonglong2 w2 = wp[q];
            asm("fma.rn.f32x2 %0, %1, %2, %0;" : "+l"(acc[2 * q]) : "l"(w2.x), "l"(h2));
            asm("fma.rn.f32x2 %0, %1, %2, %0;" : "+l"(acc[2 * q + 1]) : "l"(w2.y), "l"(h2));
        }
    }
    float* dst = out + ((size_t)b * TT + (TT - 1 - kd)) * FF;
#pragma unroll
    for (int q = 0; q < 16; ++q) {
        float2 a = *(float2*)&acc[2 * q];
        float2 bq = *(float2*)&acc[2 * q + 1];
        *(float4*)(dst + 4 * q) = make_float4(a.x, a.y, bq.x, bq.y);
    }
}

// ---------------- launch ----------------
extern "C" void kernel_launch(void* const* d_in, const int* in_sizes, int n_in,
                              void* d_out, int out_size) {
    (void)in_sizes; (void)n_in; (void)out_size;
    const float* ts       = (const float*)d_in[0];
    const float* w_ih_enc = (const float*)d_in[1];
    const float* w_hh_enc = (const float*)d_in[2];
    const float* b_ih_enc = (const float*)d_in[3];
    const float* b_hh_enc = (const float*)d_in[4];
    const float* w_ih_dec = (const float*)d_in[5];
    const float* w_hh_dec = (const float*)d_in[6];
    const float* b_ih_dec = (const float*)d_in[7];
    const float* b_hh_dec = (const float*)d_in[8];
    const float* w_out    = (const float*)d_in[9];
    const float* b_out    = (const float*)d_in[10];
    float* out = (float*)d_out;

    static bool attr_set = false;
    if (!attr_set) {
        cudaFuncSetAttribute(lstm_persistent,
                             cudaFuncAttributeMaxDynamicSharedMemorySize, SMEM_BYTES);
        attr_set = true;
    }
    reset_flags_kernel<<<1, 32>>>();
    lstm_persistent<<<NB, NT, SMEM_BYTES>>>(
        ts, w_ih_enc, w_hh_enc, b_ih_enc, b_hh_enc,
        w_ih_dec, w_hh_dec, b_ih_dec, b_hh_dec, w_out, b_out, out);
    y_final<<<TT, 128>>>(b_out, out);
}

// round 11
// speedup vs baseline: 3.2481x; 1.2588x over previous
#include <cuda_runtime.h>
#include <cuda_fp16.h>
#include <cstdint>

#define NB 128
#define NT 256          // 8 compute warps
#define BB 128
#define TT 1024
#define FF 64
#define HH 512

typedef unsigned long long ull;

// ---------------- device scratch ----------------
__device__ __align__(1024) unsigned char g_hh[2][8 * 16384];     // h fp16 chunk tiles
__device__ __align__(1024) unsigned char g_xh[(size_t)TT * 16384]; // x fp16 tiles
__device__ float g_hist[(size_t)TT * HH * BB];   // decoder-input h [kd][j][b]
__device__ float g_woutT[HH * FF];
__device__ unsigned int g_flag[8];
__device__ unsigned int g_count = 0, g_gen = 0;

// ---------------- smem byte offsets ----------------
#define OFF_WBE  0          // enc B frags: 9 ch * 4096 (hi+lo interleaved per 512B block)
#define OFF_WBD  36864      // dec B frags: 8 ch * 4096
#define OFF_A    69632      // 3 stages * 16384
#define OFF_BE   118784     // 16 floats
#define OFF_BD   118848     // 16 floats
#define SMEM_BYTES 118912

static __device__ __forceinline__ uint32_t sw128(uint32_t o) {
    return o ^ ((o >> 3) & 0x70);
}
__device__ __forceinline__ float sigf(float x) {
    return __fdividef(1.0f, 1.0f + __expf(-x));
}
__device__ __forceinline__ float tanhfast(float x) {
    return 1.0f - __fdividef(2.0f, __expf(2.0f * x) + 1.0f);
}

__device__ __forceinline__ void grid_barrier_init() {
    __syncthreads();
    if (threadIdx.x == 0) {
        unsigned int cur0;
        asm volatile("ld.acquire.gpu.b32 %0, [%1];" : "=r"(cur0) : "l"(&g_gen) : "memory");
        unsigned int target = cur0 + 1u;
        __threadfence();
        unsigned int t = atomicAdd(&g_count, 1u);
        if (t == NB - 1u) {
            g_count = 0u;
            asm volatile("st.release.gpu.b32 [%0], %1;" :: "l"(&g_gen), "r"(target) : "memory");
        } else {
            unsigned int cur;
            do {
                __nanosleep(20);
                asm volatile("ld.acquire.gpu.b32 %0, [%1];" : "=r"(cur) : "l"(&g_gen) : "memory");
            } while ((int)(cur - target) < 0);
        }
    }
    __syncthreads();
}
__device__ __forceinline__ void wait_flag(int ch, unsigned int tgt) {
    unsigned int v;
    asm volatile("ld.acquire.gpu.b32 %0, [%1];" : "=r"(v) : "l"(&g_flag[ch]) : "memory");
    while ((int)(v - tgt) < 0) {
        __nanosleep(32);
        asm volatile("ld.acquire.gpu.b32 %0, [%1];" : "=r"(v) : "l"(&g_flag[ch]) : "memory");
    }
}

// stage one 16KB fp16 chunk: 4 cp.async.cg per thread
__device__ __forceinline__ void prefetch_chunk(uint32_t dst, const unsigned char* src, int tid) {
#pragma unroll
    for (int i = 0; i < 4; i++) {
        uint32_t off = (uint32_t)(tid + NT * i) * 16u;
        asm volatile("cp.async.cg.shared.global [%0], [%1], 16;"
                     :: "r"(dst + off), "l"(src + off) : "memory");
    }
    asm volatile("cp.async.commit_group;" ::: "memory");
}

__device__ __forceinline__ void ldmx4(uint32_t addr, uint32_t* a) {
    asm volatile("ldmatrix.sync.aligned.m8n8.x4.shared.b16 {%0,%1,%2,%3}, [%4];"
                 : "=r"(a[0]), "=r"(a[1]), "=r"(a[2]), "=r"(a[3]) : "r"(addr));
}
__device__ __forceinline__ void mma16816(float* d, const uint32_t* a, uint32_t b0, uint32_t b1) {
    asm volatile(
        "mma.sync.aligned.m16n8k16.row.col.f32.f16.f16.f32 "
        "{%0,%1,%2,%3}, {%4,%5,%6,%7}, {%8,%9}, {%0,%1,%2,%3};"
        : "+f"(d[0]), "+f"(d[1]), "+f"(d[2]), "+f"(d[3])
        : "r"(a[0]), "r"(a[1]), "r"(a[2]), "r"(a[3]), "r"(b0), "r"(b1));
}
__device__ __forceinline__ uint32_t pack_h2(float lo, float hi) {
    uint32_t r;
    asm("cvt.rn.f16x2.f32 %0, %1, %2;" : "=r"(r) : "f"(hi), "f"(lo));
    return r;
}

// consume one staged chunk: 4 ldmatrix + 16 LDS.64 + 16 HMMA
__device__ __forceinline__ void consume_chunk(uint32_t sa, uint32_t wb,
                                              uint32_t abase, int lane,
                                              float* D0, float* D1) {
#pragma unroll
    for (int ks = 0; ks < 4; ++ks) {
        uint32_t ao = sw128(abase + (uint32_t)ks * 32u);
        uint32_t a[4];
        ldmx4(sa + ao, a);
#pragma unroll
        for (int nt = 0; nt < 2; ++nt) {
            uint32_t fb = wb + (uint32_t)(ks * 2 + nt) * 512u + (uint32_t)lane * 8u;
            uint32_t bh0, bh1, bl0, bl1;
            asm("ld.shared.v2.b32 {%0,%1}, [%2];" : "=r"(bh0), "=r"(bh1) : "r"(fb));
            asm("ld.shared.v2.b32 {%0,%1}, [%2];" : "=r"(bl0), "=r"(bl1) : "r"(fb + 256u));
            float* D = nt ? D1 : D0;
            mma16816(D, a, bh0, bh1);
            mma16816(D, a, bl0, bl1);
        }
    }
}

__global__ void reset_flags_kernel() {
    if (threadIdx.x < 8) g_flag[threadIdx.x] = 16u;   // h_0 ready baseline
}

__global__ void __launch_bounds__(NT, 1) lstm_persistent(
    const float* __restrict__ ts,
    const float* __restrict__ w_ih_enc, const float* __restrict__ w_hh_enc,
    const float* __restrict__ b_ih_enc, const float* __restrict__ b_hh_enc,
    const float* __restrict__ w_ih_dec, const float* __restrict__ w_hh_dec,
    const float* __restrict__ b_ih_dec, const float* __restrict__ b_hh_dec,
    const float* __restrict__ w_out, const float* __restrict__ b_out,
    float* __restrict__ out)
{
    extern __shared__ unsigned char smem[];
    const int tid = threadIdx.x;
    const int cid = blockIdx.x;
    const int jb = cid * 4;
    const int gidx = cid >> 4;
    const uint32_t sb = (uint32_t)__cvta_generic_to_shared(smem);

    // ======== INIT: encoder B fragments, fp16 hi + residual lo ========
    for (int e = tid; e < 9 * 4 * 2 * 32; e += NT) {
        int lane = e & 31, rem = e >> 5;
        int nt = rem & 1, ks = (rem >> 1) & 3, ch = rem >> 3;
        int gid = lane >> 2, tig = lane & 3;
        int n = nt * 8 + gid, jl = n >> 2, q = n & 3;
        int row = q * HH + jb + jl;
        float v[4];
#pragma unroll
        for (int d = 0; d < 4; ++d) {
            int kin = ks * 16 + 2 * tig + ((d & 2) ? 8 : 0) + (d & 1);
            v[d] = (ch < 8) ? w_hh_enc[(size_t)row * HH + ch * 64 + kin]
                            : w_ih_enc[(size_t)row * FF + kin];
        }
        float hi[4], lo[4];
#pragma unroll
        for (int d = 0; d < 4; ++d) {
            hi[d] = __half2float(__float2half_rn(v[d]));
            lo[d] = v[d] - hi[d];
        }
        uint32_t base = (uint32_t)(ch * 8 + ks * 2 + nt) * 512u + (uint32_t)lane * 8u;
        uint32_t* ph = (uint32_t*)(smem + OFF_WBE + base);
        uint32_t* pl = (uint32_t*)(smem + OFF_WBE + base + 256);
        ph[0] = pack_h2(hi[0], hi[1]); ph[1] = pack_h2(hi[2], hi[3]);
        pl[0] = pack_h2(lo[0], lo[1]); pl[1] = pack_h2(lo[2], lo[3]);
    }
    // ======== INIT: decoder fused B fragments (W_eff = w_hh + w_ih @ w_out) ========
    for (int e = tid; e < 8 * 4 * 2 * 32; e += NT) {
        int lane = e & 31, rem = e >> 5;
        int nt = rem & 1, ks = (rem >> 1) & 3, ch = rem >> 3;
        int gid = lane >> 2, tig = lane & 3;
        int n = nt * 8 + gid, jl = n >> 2, q = n & 3;
        int row = q * HH + jb + jl;
        const float* wr = w_ih_dec + (size_t)row * FF;
        float v[4];
#pragma unroll
        for (int d = 0; d < 4; ++d) {
            int k = ch * 64 + ks * 16 + 2 * tig + ((d & 2) ? 8 : 0) + (d & 1);
            float acc = w_hh_dec[(size_t)row * HH + k];
#pragma unroll 8
            for (int f = 0; f < FF; ++f) acc += wr[f] * w_out[(size_t)f * HH + k];
            v[d] = acc;
        }
        float hi[4], lo[4];
#pragma unroll
        for (int d = 0; d < 4; ++d) {
            hi[d] = __half2float(__float2half_rn(v[d]));
            lo[d] = v[d] - hi[d];
        }
        uint32_t base = (uint32_t)(ch * 8 + ks * 2 + nt) * 512u + (uint32_t)lane * 8u;
        uint32_t* ph = (uint32_t*)(smem + OFF_WBD + base);
        uint32_t* pl = (uint32_t*)(smem + OFF_WBD + base + 256);
        ph[0] = pack_h2(hi[0], hi[1]); ph[1] = pack_h2(hi[2], hi[3]);
        pl[0] = pack_h2(lo[0], lo[1]); pl[1] = pack_h2(lo[2], lo[3]);
    }
    // biases [jl][q]
    if (tid < 16) {
        int jl = tid >> 2, q = tid & 3;
        int row = q * HH + jb + jl;
        ((float*)(smem + OFF_BE))[jl * 4 + q] = b_ih_enc[row] + b_hh_enc[row];
        float v = b_ih_dec[row] + b_hh_dec[row];
        const float* wr = w_ih_dec + (size_t)row * FF;
#pragma unroll 8
        for (int f = 0; f < FF; ++f) v += wr[f] * b_out[f];
        ((float*)(smem + OFF_BD))[jl * 4 + q] = v;
    }
    // x tiles: [t][b*128B] fp16, swizzled; 8 t per CTA
    for (int tt = 0; tt < TT / NB; ++tt) {
        int t = cid * (TT / NB) + tt;
        for (int idx = tid; idx < BB * 16; idx += NT) {
            int b = idx >> 4, f4 = (idx & 15) * 4;
            float v0 = ts[((size_t)b * TT + t) * FF + f4];
            float v1 = ts[((size_t)b * TT + t) * FF + f4 + 1];
            float v2 = ts[((size_t)b * TT + t) * FF + f4 + 2];
            float v3 = ts[((size_t)b * TT + t) * FF + f4 + 3];
            uint32_t o = sw128((uint32_t)(b * 128 + f4 * 2));
            *(uint2*)(g_xh + (size_t)t * 16384 + o) =
                make_uint2(pack_h2(v0, v1), pack_h2(v2, v3));
        }
    }
    // zero own h_0 slice (4 cols x 128 b)
    if (tid < 128) {
        uint32_t o = sw128((uint32_t)(tid * 128 + (cid & 15) * 8));
        *(uint2*)(g_hh[0] + (size_t)gidx * 16384 + o) = make_uint2(0, 0);
    }
    if (cid == 0) {
        for (int idx = tid; idx < HH * FF; idx += NT) {
            int j = idx >> 6, f = idx & 63;
            g_woutT[j * FF + f] = w_out[(size_t)f * HH + j];
        }
    }
    grid_barrier_init();

    // ======== persistent recurrence ========
    const int w = tid >> 5, lane = tid & 31;
    const int gid = lane >> 2, tig = lane & 3;
    const uint32_t abase = (uint32_t)(((w << 4) + (lane & 15)) * 128 + ((lane >> 4) & 1) * 16);

    float c0s = 0.0f, c8s = 0.0f;

    for (int s = 0; s < 2 * TT; ++s) {
        const bool enc = (s < TT);
        const int nc = enc ? 9 : 8;
        if (s == TT) { c0s = 0.0f; c8s = 0.0f; }
        const unsigned int tgt = 16u * (unsigned)(s + 1);

        if (tid < 8) wait_flag(tid, tgt);    // parallel upfront wait
        __syncthreads();

        const unsigned char* hh = g_hh[s & 1];
#define SRC(i) (enc ? ((i) == 0 ? g_xh + (size_t)s * 16384 : hh + (size_t)((i) - 1) * 16384) \
                    : hh + (size_t)(i) * 16384)

        prefetch_chunk(sb + OFF_A, SRC(0), tid);
        prefetch_chunk(sb + OFF_A + 16384u, SRC(1), tid);

        float D0[4] = {0, 0, 0, 0}, D1[4] = {0, 0, 0, 0};

        for (int i = 0; i < nc; ++i) {
            if (i + 1 < nc) {
                asm volatile("cp.async.wait_group 1;" ::: "memory");
            } else {
                asm volatile("cp.async.wait_group 0;" ::: "memory");
            }
            __syncthreads();   // chunk i landed; stage (i+2)%3 free
            if (i + 2 < nc) {
                prefetch_chunk(sb + OFF_A + (uint32_t)((i + 2) % 3) * 16384u, SRC(i + 2), tid);
            }
            int ch = enc ? (i == 0 ? 8 : i - 1) : i;
            uint32_t wb = sb + (enc ? OFF_WBE : OFF_WBD) + (uint32_t)ch * 4096u;
            consume_chunk(sb + OFF_A + (uint32_t)(i % 3) * 16384u, wb, abase, lane, D0, D1);
        }
#undef SRC

        // ---- epilogue: gate pairing via shfl, cell update ----
        bool ev = ((tig & 1) == 0);
        float s0 = ev ? D1[0] : D0[0];
        float s1 = ev ? D1[1] : D0[1];
        float s2 = ev ? D1[2] : D0[2];
        float s3 = ev ? D1[3] : D0[3];
        float r0 = __shfl_xor_sync(0xffffffffu, s0, 1);
        float r1 = __shfl_xor_sync(0xffffffffu, s1, 1);
        float r2 = __shfl_xor_sync(0xffffffffu, s2, 1);
        float r3 = __shfl_xor_sync(0xffffffffu, s3, 1);
        float gi0, gf0, gi8, gf8, gg0, go0, gg8, go8;
        int jl;
        if (ev) {
            gi0 = D0[0]; gf0 = D0[1]; gi8 = D0[2]; gf8 = D0[3];
            gg0 = r0; go0 = r1; gg8 = r2; go8 = r3;
            jl = tig >> 1;
        } else {
            gi0 = r0; gf0 = r1; gi8 = r2; gf8 = r3;
            gg0 = D1[0]; go0 = D1[1]; gg8 = D1[2]; go8 = D1[3];
            jl = (tig >> 1) + 2;
        }
        float4 bi = ((const float4*)(smem + (enc ? OFF_BE : OFF_BD)))[jl];
        float iv0 = sigf(gi0 + bi.x), fv0 = sigf(gf0 + bi.y);
        float gv0 = tanhfast(gg0 + bi.z), ov0 = sigf(go0 + bi.w);
        float iv8 = sigf(gi8 + bi.x), fv8 = sigf(gf8 + bi.y);
        float gv8 = tanhfast(gg8 + bi.z), ov8 = sigf(go8 + bi.w);
        c0s = fv0 * c0s + iv0 * gv0;
        c8s = fv8 * c8s + iv8 * gv8;
        float h0 = ov0 * tanhfast(c0s);
        float h8 = ov8 * tanhfast(c8s);

        int b0r = (w << 4) + gid;
        uint32_t colb = (uint32_t)((((cid & 15) << 2) + jl) << 1);
        uint32_t o0 = sw128((uint32_t)(b0r * 128) + colb);
        uint32_t o8 = sw128((uint32_t)((b0r + 8) * 128) + colb);
        int nb2 = (s + 1) & 1;
        size_t tb = (size_t)gidx * 16384;
        *(__half*)(g_hh[nb2] + tb + o0) = __float2half_rn(h0);
        *(__half*)(g_hh[nb2] + tb + o8) = __float2half_rn(h8);
        if (s >= TT - 1 && s < 2 * TT - 1) {
            int kd = s - (TT - 1);
            float* hb = g_hist + ((size_t)kd * HH + (jb + jl)) * BB;
            hb[b0r] = h0;
            hb[b0r + 8] = h8;
        }
        __syncthreads();
        if (tid == 0) {
            __threadfence();
            atomicAdd(&g_flag[gidx], 1u);
        }
    }
}

// ============ final y pass: out[b][T-1-kd][:] = hist[kd]·w_outT + b_out ============
__global__ void __launch_bounds__(128) y_final(const float* __restrict__ b_out,
                                               float* __restrict__ out) {
    const int kd = blockIdx.x;
    const int b = threadIdx.x;
    ull acc[32];
#pragma unroll
    for (int q = 0; q < 32; ++q) {
        float2 bo = *(const float2*)(b_out + 2 * q);
        asm("mov.b64 %0, {%1, %2};" : "=l"(acc[q]) : "f"(bo.x), "f"(bo.y));
    }
    const float* hp = g_hist + (size_t)kd * HH * BB + b;
#pragma unroll 4
    for (int j = 0; j < HH; ++j) {
        float hv = hp[(size_t)j * BB];
        ull h2;
        asm("mov.b64 %0, {%1, %2};" : "=l"(h2) : "f"(hv), "f"(hv));
        const ulonglong2* wp = (const ulonglong2*)(g_woutT + j * FF);
#pragma unroll
        for (int q = 0; q < 16; ++q) {
            ulonglong2 w2 = wp[q];
            asm("fma.rn.f32x2 %0, %1, %2, %0;" : "+l"(acc[2 * q]) : "l"(w2.x), "l"(h2));
            asm("fma.rn.f32x2 %0, %1, %2, %0;" : "+l"(acc[2 * q + 1]) : "l"(w2.y), "l"(h2));
        }
    }
    float* dst = out + ((size_t)b * TT + (TT - 1 - kd)) * FF;
#pragma unroll
    for (int q = 0; q < 16; ++q) {
        float2 a = *(float2*)&acc[2 * q];
        float2 bq = *(float2*)&acc[2 * q + 1];
        *(float4*)(dst + 4 * q) = make_float4(a.x, a.y, bq.x, bq.y);
    }
}

// ---------------- launch ----------------
extern "C" void kernel_launch(void* const* d_in, const int* in_sizes, int n_in,
                              void* d_out, int out_size) {
    (void)in_sizes; (void)n_in; (void)out_size;
    const float* ts       = (const float*)d_in[0];
    const float* w_ih_enc = (const float*)d_in[1];
    const float* w_hh_enc = (const float*)d_in[2];
    const float* b_ih_enc = (const float*)d_in[3];
    const float* b_hh_enc = (const float*)d_in[4];
    const float* w_ih_dec = (const float*)d_in[5];
    const float* w_hh_dec = (const float*)d_in[6];
    const float* b_ih_dec = (const float*)d_in[7];
    const float* b_hh_dec = (const float*)d_in[8];
    const float* w_out    = (const float*)d_in[9];
    const float* b_out    = (const float*)d_in[10];
    float* out = (float*)d_out;

    static bool attr_set = false;
    if (!attr_set) {
        cudaFuncSetAttribute(lstm_persistent,
                             cudaFuncAttributeMaxDynamicSharedMemorySize, SMEM_BYTES);
        attr_set = true;
    }
    reset_flags_kernel<<<1, 32>>>();
    lstm_persistent<<<NB, NT, SMEM_BYTES>>>(
        ts, w_ih_enc, w_hh_enc, b_ih_enc, b_hh_enc,
        w_ih_dec, w_hh_dec, b_ih_dec, b_hh_dec, w_out, b_out, out);
    y_final<<<TT, 128>>>(b_out, out);
}